// round 8
// baseline (speedup 1.0000x reference)
#include <cuda_runtime.h>
#include <math.h>

// ---------------------------------------------------------------------------
// Problem constants
// ---------------------------------------------------------------------------
#define BATCH 64
#define HDIM  1024
#define EDIM  512
#define VDIM  50000
#define LQ    32
#define LD    400

// Output layout (tuple concat, float32):
// out[B,V], h1[1,B,H], c1, dh, dc, doc_w[B,1,LD]
#define OFF_OUT   0
#define OFF_H1    (3200000)
#define OFF_C1    (OFF_H1 + 65536)
#define OFF_DH    (OFF_C1 + 65536)
#define OFF_DC    (OFF_DH + 65536)
#define OFF_DOCW  (OFF_DC + 65536)

// ---------------------------------------------------------------------------
// Scratch (device globals: no allocations allowed)
// ---------------------------------------------------------------------------
__device__ float g_qpart [BATCH * HDIM];          // h_last @ W_qa_h^T
__device__ float g_partq [LQ * BATCH * 8];        // query score partials (8 n-blocks)
__device__ float g_wq    [BATCH * LQ];            // query attn weights
__device__ float g_docq  [BATCH * 2 * HDIM];      // [h_last | q_ctx]
__device__ float g_dqpart[BATCH * HDIM];          // doc_query @ W_da_h^T
__device__ float g_partd [LD * BATCH * 8];        // doc score partials
__device__ float g_wd    [BATCH * LD];            // doc attn weights
__device__ float g_xcat  [BATCH * 1536];          // [embedded(512) | doc_ctx(1024)]
__device__ float g_xout  [BATCH * 2048];          // [h1 | doc_ctx]
__device__ float g_gates [BATCH * 4096];
__device__ float g_dgates[BATCH * 4096];

// ---------------------------------------------------------------------------
// Generic NT SGEMM: C[M,N] = A[M,K] * W[N,K]^T  (both K-contiguous)
// FUSED=false : C = acc (+bias1[n]) (+bias2[n]) (+= C if accC)
// FUSED=true  : per-row partial of  sum_n tanh(acc + qadd[b,n] + bias1[n])*v[n]
//               written deterministically to part[m*gridDim.x + blockIdx.x]
//               (b = m % 64; requires N-tiles exactly covering N=1024, BN/TN==16)
// ---------------------------------------------------------------------------
template<int BM, int BN, int BK, int TM, int TN, bool FUSED>
__global__ __launch_bounds__((BM/TM)*(BN/TN))
void gemm_nt(const float* __restrict__ A, int lda,
             const float* __restrict__ W, int ldw,
             float* __restrict__ C, int ldc,
             int M, int N, int K,
             const float* __restrict__ bias1,
             const float* __restrict__ bias2,
             int accC,
             const float* __restrict__ qadd,
             const float* __restrict__ vvec,
             float* __restrict__ part)
{
    constexpr int NTH = (BM / TM) * (BN / TN);
    constexpr int TX  = BN / TN;
    __shared__ float As[BK][BM];
    __shared__ float Bs[BK][BN];

    const int tid = threadIdx.x;
    const int tx  = tid % TX;
    const int ty  = tid / TX;
    const int m0  = blockIdx.y * BM;
    const int n0  = blockIdx.x * BN;

    float acc[TM][TN];
#pragma unroll
    for (int i = 0; i < TM; i++)
#pragma unroll
        for (int j = 0; j < TN; j++) acc[i][j] = 0.f;

    constexpr int LA = (BM * BK / 4) / NTH;
    constexpr int LB = (BN * BK / 4) / NTH;

    for (int k0 = 0; k0 < K; k0 += BK) {
#pragma unroll
        for (int i = 0; i < LA; i++) {
            int s   = i * NTH + tid;
            int row = s / (BK / 4);
            int kq  = s % (BK / 4);
            float4 a;
            if (m0 + row < M)
                a = *reinterpret_cast<const float4*>(A + (size_t)(m0 + row) * lda + k0 + kq * 4);
            else
                a = make_float4(0.f, 0.f, 0.f, 0.f);
            As[kq * 4 + 0][row] = a.x; As[kq * 4 + 1][row] = a.y;
            As[kq * 4 + 2][row] = a.z; As[kq * 4 + 3][row] = a.w;
        }
#pragma unroll
        for (int i = 0; i < LB; i++) {
            int s   = i * NTH + tid;
            int row = s / (BK / 4);
            int kq  = s % (BK / 4);
            float4 b;
            if (n0 + row < N)
                b = *reinterpret_cast<const float4*>(W + (size_t)(n0 + row) * ldw + k0 + kq * 4);
            else
                b = make_float4(0.f, 0.f, 0.f, 0.f);
            Bs[kq * 4 + 0][row] = b.x; Bs[kq * 4 + 1][row] = b.y;
            Bs[kq * 4 + 2][row] = b.z; Bs[kq * 4 + 3][row] = b.w;
        }
        __syncthreads();

#pragma unroll
        for (int k = 0; k < BK; k++) {
            float4 av4[TM / 4];
            float4 bv4[TN / 4];
#pragma unroll
            for (int q = 0; q < TM / 4; q++)
                av4[q] = *reinterpret_cast<const float4*>(&As[k][ty * TM + q * 4]);
#pragma unroll
            for (int q = 0; q < TN / 4; q++)
                bv4[q] = *reinterpret_cast<const float4*>(&Bs[k][tx * TN + q * 4]);
            const float* av = reinterpret_cast<const float*>(av4);
            const float* bv = reinterpret_cast<const float*>(bv4);
#pragma unroll
            for (int i = 0; i < TM; i++)
#pragma unroll
                for (int j = 0; j < TN; j++)
                    acc[i][j] = fmaf(av[i], bv[j], acc[i][j]);
        }
        __syncthreads();
    }

    if constexpr (!FUSED) {
#pragma unroll
        for (int i = 0; i < TM; i++) {
            int m = m0 + ty * TM + i;
            if (m >= M) continue;
#pragma unroll
            for (int j = 0; j < TN; j++) {
                int n = n0 + tx * TN + j;
                if (n >= N) continue;
                float r = acc[i][j];
                if (bias1) r += bias1[n];
                if (bias2) r += bias2[n];
                if (accC)  r += C[(size_t)m * ldc + n];
                C[(size_t)m * ldc + n] = r;
            }
        }
    } else {
        // TX must be 16 so each row's partial lives in a contiguous 16-lane group.
#pragma unroll
        for (int i = 0; i < TM; i++) {
            int m = m0 + ty * TM + i;
            int b = m & (BATCH - 1);
            float p = 0.f;
#pragma unroll
            for (int j = 0; j < TN; j++) {
                int n   = n0 + tx * TN + j;
                float e = tanhf(acc[i][j] + qadd[b * HDIM + n] + bias1[n]);
                p = fmaf(e, vvec[n], p);
            }
            p += __shfl_xor_sync(0xffffffffu, p, 1);
            p += __shfl_xor_sync(0xffffffffu, p, 2);
            p += __shfl_xor_sync(0xffffffffu, p, 4);
            p += __shfl_xor_sync(0xffffffffu, p, 8);
            if (tx == 0 && m < M)
                part[(size_t)m * gridDim.x + blockIdx.x] = p;
        }
    }
}

// ---------------------------------------------------------------------------
// Small helper kernels
// ---------------------------------------------------------------------------
__global__ void gather_embed(const int* __restrict__ idx,
                             const float* __restrict__ embed,
                             float* __restrict__ xcat)
{
    int b = blockIdx.x, e = threadIdx.x;              // 512 threads
    xcat[b * 1536 + e] = embed[(size_t)idx[b] * EDIM + e];
}

__global__ void copy_hlast(const float* __restrict__ h0, float* __restrict__ docq)
{
    int b = blockIdx.x, h = threadIdx.x;              // 1024 threads
    docq[b * 2048 + h] = h0[b * HDIM + h];
}

__global__ void qsoftmax(const float* __restrict__ part, float* __restrict__ w)
{
    int b = blockIdx.x, t = threadIdx.x;              // 32 threads
    const float* p = part + ((size_t)t * BATCH + b) * 8;
    float s = p[0] + p[1] + p[2] + p[3] + p[4] + p[5] + p[6] + p[7];
    float mx = s;
#pragma unroll
    for (int o = 16; o; o >>= 1) mx = fmaxf(mx, __shfl_xor_sync(0xffffffffu, mx, o));
    float e = expf(s - mx);
    float sum = e;
#pragma unroll
    for (int o = 16; o; o >>= 1) sum += __shfl_xor_sync(0xffffffffu, sum, o);
    w[b * LQ + t] = e / sum;
}

__global__ void dsoftmax(const float* __restrict__ part,
                         float* __restrict__ w, float* __restrict__ outw)
{
    __shared__ float sh[256];
    int b = blockIdx.x, tid = threadIdx.x;            // 256 threads
    float mx = -1e30f;
    for (int t = tid; t < LD; t += 256) {
        const float* p = part + ((size_t)t * BATCH + b) * 8;
        float s = p[0] + p[1] + p[2] + p[3] + p[4] + p[5] + p[6] + p[7];
        mx = fmaxf(mx, s);
    }
    sh[tid] = mx; __syncthreads();
    for (int s = 128; s > 0; s >>= 1) { if (tid < s) sh[tid] = fmaxf(sh[tid], sh[tid + s]); __syncthreads(); }
    mx = sh[0]; __syncthreads();

    float sum = 0.f;
    for (int t = tid; t < LD; t += 256) {
        const float* p = part + ((size_t)t * BATCH + b) * 8;
        float s = p[0] + p[1] + p[2] + p[3] + p[4] + p[5] + p[6] + p[7];
        sum += expf(s - mx);
    }
    sh[tid] = sum; __syncthreads();
    for (int s = 128; s > 0; s >>= 1) { if (tid < s) sh[tid] += sh[tid + s]; __syncthreads(); }
    float tot = sh[0];

    for (int t = tid; t < LD; t += 256) {
        const float* p = part + ((size_t)t * BATCH + b) * 8;
        float s = p[0] + p[1] + p[2] + p[3] + p[4] + p[5] + p[6] + p[7];
        float v = expf(s - mx) / tot;
        w[b * LD + t]    = v;
        outw[b * LD + t] = v;
    }
}

// ctx[b,h] = sum_t w[b,t] * enc[t,b,h]; written to up to two destinations
__global__ void weighted_ctx(const float* __restrict__ w, int T,
                             const float* __restrict__ enc,
                             float* __restrict__ dst1, int ld1, int off1,
                             float* __restrict__ dst2, int ld2, int off2)
{
    int b = blockIdx.y;
    int h = blockIdx.x * blockDim.x + threadIdx.x;
    const float* wb = w + b * T;
    float a = 0.f;
    for (int t = 0; t < T; t++)
        a = fmaf(wb[t], enc[((size_t)t * BATCH + b) * HDIM + h], a);
    dst1[(size_t)b * ld1 + off1 + h] = a;
    if (dst2) dst2[(size_t)b * ld2 + off2 + h] = a;
}

__device__ __forceinline__ float sigf(float x) { return 1.f / (1.f + expf(-x)); }

__global__ void lstm_cell(const float* __restrict__ gates,
                          const float* __restrict__ cprev,
                          float* __restrict__ hout, float* __restrict__ cout,
                          float* __restrict__ hout2)   // optional, ld=2048 off=0
{
    int idx = blockIdx.x * blockDim.x + threadIdx.x;  // B*H
    int b = idx >> 10, h = idx & 1023;
    const float* g = gates + b * 4096;
    float i  = sigf(g[h]);
    float f  = sigf(g[1024 + h]);
    float gg = tanhf(g[2048 + h]);
    float o  = sigf(g[3072 + h]);
    float c  = f * cprev[idx] + i * gg;
    float hh = o * tanhf(c);
    hout[idx] = hh;
    cout[idx] = c;
    if (hout2) hout2[b * 2048 + h] = hh;
}

__global__ void logsoftmax_rows(float* __restrict__ x)
{
    __shared__ float sh[512];
    int b = blockIdx.x, tid = threadIdx.x;            // 512 threads
    float* row = x + (size_t)b * VDIM;

    float mx = -1e30f;
    for (int i = tid; i < VDIM; i += 512) mx = fmaxf(mx, row[i]);
    sh[tid] = mx; __syncthreads();
    for (int s = 256; s > 0; s >>= 1) { if (tid < s) sh[tid] = fmaxf(sh[tid], sh[tid + s]); __syncthreads(); }
    mx = sh[0]; __syncthreads();

    float sum = 0.f;
    for (int i = tid; i < VDIM; i += 512) sum += expf(row[i] - mx);
    sh[tid] = sum; __syncthreads();
    for (int s = 256; s > 0; s >>= 1) { if (tid < s) sh[tid] += sh[tid + s]; __syncthreads(); }
    float lse = mx + logf(sh[0]);

    for (int i = tid; i < VDIM; i += 512) row[i] -= lse;
}

// ---------------------------------------------------------------------------
// Launcher
// ---------------------------------------------------------------------------
extern "C" void kernel_launch(void* const* d_in, const int* in_sizes, int n_in,
                              void* d_out, int out_size)
{
    (void)in_sizes; (void)n_in; (void)out_size;
    const int*   input = (const int*)  d_in[0];
    const float* h0    = (const float*)d_in[1];
    const float* c0    = (const float*)d_in[2];
    const float* dh0   = (const float*)d_in[3];
    const float* dc0   = (const float*)d_in[4];
    const float* qo    = (const float*)d_in[5];
    const float* enc   = (const float*)d_in[6];
    const float* embed = (const float*)d_in[7];
    const float* W_qa  = (const float*)d_in[8];
    const float* b_qa  = (const float*)d_in[9];
    const float* v_q   = (const float*)d_in[10];
    const float* W_da  = (const float*)d_in[11];
    const float* b_da  = (const float*)d_in[12];
    const float* v_d   = (const float*)d_in[13];
    const float* W_ih  = (const float*)d_in[14];
    const float* W_hh  = (const float*)d_in[15];
    const float* b_ih  = (const float*)d_in[16];
    const float* b_hh  = (const float*)d_in[17];
    const float* Wd_ih = (const float*)d_in[18];
    const float* Wd_hh = (const float*)d_in[19];
    const float* bd_ih = (const float*)d_in[20];
    const float* bd_hh = (const float*)d_in[21];
    const float* W_out = (const float*)d_in[22];
    const float* b_out = (const float*)d_in[23];
    float* out = (float*)d_out;

    float *qpart, *partq, *wq, *docq, *dqpart, *partd, *wd, *xcat, *xout, *gates, *dgates;
    cudaGetSymbolAddress((void**)&qpart,  g_qpart);
    cudaGetSymbolAddress((void**)&partq,  g_partq);
    cudaGetSymbolAddress((void**)&wq,     g_wq);
    cudaGetSymbolAddress((void**)&docq,   g_docq);
    cudaGetSymbolAddress((void**)&dqpart, g_dqpart);
    cudaGetSymbolAddress((void**)&partd,  g_partd);
    cudaGetSymbolAddress((void**)&wd,     g_wd);
    cudaGetSymbolAddress((void**)&xcat,   g_xcat);
    cudaGetSymbolAddress((void**)&xout,   g_xout);
    cudaGetSymbolAddress((void**)&gates,  g_gates);
    cudaGetSymbolAddress((void**)&dgates, g_dgates);

    // Embedding gather into xcat[:, 0:512]; docq[:, 0:1024] = h_last
    gather_embed<<<BATCH, 512>>>(input, embed, xcat);
    copy_hlast  <<<BATCH, 1024>>>(h0, docq);

    // ---- Query attention ----
    // qpart = h_last @ W_qa[:, :H]^T
    gemm_nt<64,128,16,4,8,false><<<dim3(8,1),256>>>(
        h0, HDIM, W_qa, 2*HDIM, qpart, HDIM, BATCH, HDIM, HDIM,
        nullptr, nullptr, 0, nullptr, nullptr, nullptr);
    // fused energy + score partials over query_outputs
    gemm_nt<128,128,16,8,8,true><<<dim3(8, LQ*BATCH/128),256>>>(
        qo, HDIM, W_qa + HDIM, 2*HDIM, nullptr, 0, LQ*BATCH, HDIM, HDIM,
        b_qa, nullptr, 0, qpart, v_q, partq);
    qsoftmax<<<BATCH, 32>>>(partq, wq);
    weighted_ctx<<<dim3(HDIM/256, BATCH), 256>>>(wq, LQ, qo,
        docq, 2048, 1024, nullptr, 0, 0);

    // ---- Doc attention ----
    // dqpart = [h_last | q_ctx] @ W_da[:, :2H]^T
    gemm_nt<64,128,16,4,8,false><<<dim3(8,1),256>>>(
        docq, 2048, W_da, 3*HDIM, dqpart, HDIM, BATCH, HDIM, 2*HDIM,
        nullptr, nullptr, 0, nullptr, nullptr, nullptr);
    gemm_nt<128,128,16,8,8,true><<<dim3(8, LD*BATCH/128),256>>>(
        enc, HDIM, W_da + 2*HDIM, 3*HDIM, nullptr, 0, LD*BATCH, HDIM, HDIM,
        b_da, nullptr, 0, dqpart, v_d, partd);
    dsoftmax<<<BATCH, 256>>>(partd, wd, out + OFF_DOCW);
    weighted_ctx<<<dim3(HDIM/256, BATCH), 256>>>(wd, LD, enc,
        xcat, 1536, 512, xout, 2048, 1024);

    // ---- Distraction LSTM: dgates = doc_ctx@Wd_ih^T + dh0@Wd_hh^T + biases ----
    gemm_nt<64,128,16,4,8,false><<<dim3(32,1),256>>>(
        xcat + 512, 1536, Wd_ih, HDIM, dgates, 4096, BATCH, 4096, HDIM,
        nullptr, nullptr, 0, nullptr, nullptr, nullptr);
    gemm_nt<64,128,16,4,8,false><<<dim3(32,1),256>>>(
        dh0, HDIM, Wd_hh, HDIM, dgates, 4096, BATCH, 4096, HDIM,
        bd_ih, bd_hh, 1, nullptr, nullptr, nullptr);
    lstm_cell<<<BATCH*HDIM/256, 256>>>(dgates, dc0, out + OFF_DH, out + OFF_DC, nullptr);

    // ---- Main LSTM: gates = [emb|doc_ctx]@W_ih^T + h0@W_hh^T + biases ----
    gemm_nt<64,128,16,4,8,false><<<dim3(32,1),256>>>(
        xcat, 1536, W_ih, 1536, gates, 4096, BATCH, 4096, 1536,
        nullptr, nullptr, 0, nullptr, nullptr, nullptr);
    gemm_nt<64,128,16,4,8,false><<<dim3(32,1),256>>>(
        h0, HDIM, W_hh, HDIM, gates, 4096, BATCH, 4096, HDIM,
        b_ih, b_hh, 1, nullptr, nullptr, nullptr);
    lstm_cell<<<BATCH*HDIM/256, 256>>>(gates, c0, out + OFF_H1, out + OFF_C1, xout);

    // ---- Output projection + log_softmax ----
    gemm_nt<64,128,16,4,8,false><<<dim3((VDIM+127)/128, 1),256>>>(
        xout, 2048, W_out, 2048, out, VDIM, BATCH, VDIM, 2048,
        b_out, nullptr, 0, nullptr, nullptr, nullptr);
    logsoftmax_rows<<<BATCH, 512>>>(out);
}

// round 9
// speedup vs baseline: 1.0002x; 1.0002x over previous
#include <cuda_runtime.h>
#include <math.h>

// ---------------------------------------------------------------------------
// Problem constants
// ---------------------------------------------------------------------------
#define BATCH 64
#define HDIM  1024
#define EDIM  512
#define VDIM  50000
#define LQ    32
#define LD    400

// Output layout (tuple concat, float32):
// out[B,V], h1[1,B,H], c1, dh, dc, doc_w[B,1,LD]
#define OFF_OUT   0
#define OFF_H1    (3200000)
#define OFF_C1    (OFF_H1 + 65536)
#define OFF_DH    (OFF_C1 + 65536)
#define OFF_DC    (OFF_DH + 65536)
#define OFF_DOCW  (OFF_DC + 65536)

// ---------------------------------------------------------------------------
// Scratch (device globals: no allocations allowed)
// ---------------------------------------------------------------------------
__device__ float g_qpart [BATCH * HDIM];          // h_last @ W_qa_h^T
__device__ float g_partq [LQ * BATCH * 8];        // query score partials (8 n-blocks)
__device__ float g_wq    [BATCH * LQ];            // query attn weights
__device__ float g_docq  [BATCH * 2 * HDIM];      // [h_last | q_ctx]
__device__ float g_dqpart[BATCH * HDIM];          // doc_query @ W_da_h^T
__device__ float g_partd [LD * BATCH * 8];        // doc score partials
__device__ float g_wd    [BATCH * LD];            // doc attn weights
__device__ float g_xcat  [BATCH * 1536];          // [embedded(512) | doc_ctx(1024)]
__device__ float g_xout  [BATCH * 2048];          // [h1 | doc_ctx]
__device__ float g_gates [BATCH * 4096];
__device__ float g_dgates[BATCH * 4096];

// ---------------------------------------------------------------------------
// Generic NT SGEMM: C[M,N] = A[M,K] * W[N,K]^T  (both K-contiguous)
// FUSED=false : C = acc (+bias1[n]) (+bias2[n]) (+= C if accC)
// FUSED=true  : per-row partial of  sum_n tanh(acc + qadd[b,n] + bias1[n])*v[n]
//               written deterministically to part[m*gridDim.x + blockIdx.x]
//               (b = m % 64; requires N-tiles exactly covering N=1024, BN/TN==16)
// ---------------------------------------------------------------------------
template<int BM, int BN, int BK, int TM, int TN, bool FUSED>
__global__ __launch_bounds__((BM/TM)*(BN/TN))
void gemm_nt(const float* __restrict__ A, int lda,
             const float* __restrict__ W, int ldw,
             float* __restrict__ C, int ldc,
             int M, int N, int K,
             const float* __restrict__ bias1,
             const float* __restrict__ bias2,
             int accC,
             const float* __restrict__ qadd,
             const float* __restrict__ vvec,
             float* __restrict__ part)
{
    constexpr int NTH = (BM / TM) * (BN / TN);
    constexpr int TX  = BN / TN;
    __shared__ float As[BK][BM];
    __shared__ float Bs[BK][BN];

    const int tid = threadIdx.x;
    const int tx  = tid % TX;
    const int ty  = tid / TX;
    const int m0  = blockIdx.y * BM;
    const int n0  = blockIdx.x * BN;

    float acc[TM][TN];
#pragma unroll
    for (int i = 0; i < TM; i++)
#pragma unroll
        for (int j = 0; j < TN; j++) acc[i][j] = 0.f;

    constexpr int LA = (BM * BK / 4) / NTH;
    constexpr int LB = (BN * BK / 4) / NTH;

    for (int k0 = 0; k0 < K; k0 += BK) {
#pragma unroll
        for (int i = 0; i < LA; i++) {
            int s   = i * NTH + tid;
            int row = s / (BK / 4);
            int kq  = s % (BK / 4);
            float4 a;
            if (m0 + row < M)
                a = *reinterpret_cast<const float4*>(A + (size_t)(m0 + row) * lda + k0 + kq * 4);
            else
                a = make_float4(0.f, 0.f, 0.f, 0.f);
            As[kq * 4 + 0][row] = a.x; As[kq * 4 + 1][row] = a.y;
            As[kq * 4 + 2][row] = a.z; As[kq * 4 + 3][row] = a.w;
        }
#pragma unroll
        for (int i = 0; i < LB; i++) {
            int s   = i * NTH + tid;
            int row = s / (BK / 4);
            int kq  = s % (BK / 4);
            float4 b;
            if (n0 + row < N)
                b = *reinterpret_cast<const float4*>(W + (size_t)(n0 + row) * ldw + k0 + kq * 4);
            else
                b = make_float4(0.f, 0.f, 0.f, 0.f);
            Bs[kq * 4 + 0][row] = b.x; Bs[kq * 4 + 1][row] = b.y;
            Bs[kq * 4 + 2][row] = b.z; Bs[kq * 4 + 3][row] = b.w;
        }
        __syncthreads();

#pragma unroll
        for (int k = 0; k < BK; k++) {
            float4 av4[TM / 4];
            float4 bv4[TN / 4];
#pragma unroll
            for (int q = 0; q < TM / 4; q++)
                av4[q] = *reinterpret_cast<const float4*>(&As[k][ty * TM + q * 4]);
#pragma unroll
            for (int q = 0; q < TN / 4; q++)
                bv4[q] = *reinterpret_cast<const float4*>(&Bs[k][tx * TN + q * 4]);
            const float* av = reinterpret_cast<const float*>(av4);
            const float* bv = reinterpret_cast<const float*>(bv4);
#pragma unroll
            for (int i = 0; i < TM; i++)
#pragma unroll
                for (int j = 0; j < TN; j++)
                    acc[i][j] = fmaf(av[i], bv[j], acc[i][j]);
        }
        __syncthreads();
    }

    if constexpr (!FUSED) {
#pragma unroll
        for (int i = 0; i < TM; i++) {
            int m = m0 + ty * TM + i;
            if (m >= M) continue;
#pragma unroll
            for (int j = 0; j < TN; j++) {
                int n = n0 + tx * TN + j;
                if (n >= N) continue;
                float r = acc[i][j];
                if (bias1) r += bias1[n];
                if (bias2) r += bias2[n];
                if (accC)  r += C[(size_t)m * ldc + n];
                C[(size_t)m * ldc + n] = r;
            }
        }
    } else {
        // TX must be 16 so each row's partial lives in a contiguous 16-lane group.
#pragma unroll
        for (int i = 0; i < TM; i++) {
            int m = m0 + ty * TM + i;
            int b = m & (BATCH - 1);
            float p = 0.f;
#pragma unroll
            for (int j = 0; j < TN; j++) {
                int n   = n0 + tx * TN + j;
                float e = tanhf(acc[i][j] + qadd[b * HDIM + n] + bias1[n]);
                p = fmaf(e, vvec[n], p);
            }
            p += __shfl_xor_sync(0xffffffffu, p, 1);
            p += __shfl_xor_sync(0xffffffffu, p, 2);
            p += __shfl_xor_sync(0xffffffffu, p, 4);
            p += __shfl_xor_sync(0xffffffffu, p, 8);
            if (tx == 0 && m < M)
                part[(size_t)m * gridDim.x + blockIdx.x] = p;
        }
    }
}

// ---------------------------------------------------------------------------
// Small helper kernels
// ---------------------------------------------------------------------------
__global__ void gather_embed(const int* __restrict__ idx,
                             const float* __restrict__ embed,
                             float* __restrict__ xcat)
{
    int b = blockIdx.x, e = threadIdx.x;              // 512 threads
    xcat[b * 1536 + e] = embed[(size_t)idx[b] * EDIM + e];
}

__global__ void copy_hlast(const float* __restrict__ h0, float* __restrict__ docq)
{
    int b = blockIdx.x, h = threadIdx.x;              // 1024 threads
    docq[b * 2048 + h] = h0[b * HDIM + h];
}

__global__ void qsoftmax(const float* __restrict__ part, float* __restrict__ w)
{
    int b = blockIdx.x, t = threadIdx.x;              // 32 threads
    const float* p = part + ((size_t)t * BATCH + b) * 8;
    float s = p[0] + p[1] + p[2] + p[3] + p[4] + p[5] + p[6] + p[7];
    float mx = s;
#pragma unroll
    for (int o = 16; o; o >>= 1) mx = fmaxf(mx, __shfl_xor_sync(0xffffffffu, mx, o));
    float e = expf(s - mx);
    float sum = e;
#pragma unroll
    for (int o = 16; o; o >>= 1) sum += __shfl_xor_sync(0xffffffffu, sum, o);
    w[b * LQ + t] = e / sum;
}

__global__ void dsoftmax(const float* __restrict__ part,
                         float* __restrict__ w, float* __restrict__ outw)
{
    __shared__ float sh[256];
    int b = blockIdx.x, tid = threadIdx.x;            // 256 threads
    float mx = -1e30f;
    for (int t = tid; t < LD; t += 256) {
        const float* p = part + ((size_t)t * BATCH + b) * 8;
        float s = p[0] + p[1] + p[2] + p[3] + p[4] + p[5] + p[6] + p[7];
        mx = fmaxf(mx, s);
    }
    sh[tid] = mx; __syncthreads();
    for (int s = 128; s > 0; s >>= 1) { if (tid < s) sh[tid] = fmaxf(sh[tid], sh[tid + s]); __syncthreads(); }
    mx = sh[0]; __syncthreads();

    float sum = 0.f;
    for (int t = tid; t < LD; t += 256) {
        const float* p = part + ((size_t)t * BATCH + b) * 8;
        float s = p[0] + p[1] + p[2] + p[3] + p[4] + p[5] + p[6] + p[7];
        sum += expf(s - mx);
    }
    sh[tid] = sum; __syncthreads();
    for (int s = 128; s > 0; s >>= 1) { if (tid < s) sh[tid] += sh[tid + s]; __syncthreads(); }
    float tot = sh[0];

    for (int t = tid; t < LD; t += 256) {
        const float* p = part + ((size_t)t * BATCH + b) * 8;
        float s = p[0] + p[1] + p[2] + p[3] + p[4] + p[5] + p[6] + p[7];
        float v = expf(s - mx) / tot;
        w[b * LD + t]    = v;
        outw[b * LD + t] = v;
    }
}

// ctx[b,h] = sum_t w[b,t] * enc[t,b,h]; written to up to two destinations
__global__ void weighted_ctx(const float* __restrict__ w, int T,
                             const float* __restrict__ enc,
                             float* __restrict__ dst1, int ld1, int off1,
                             float* __restrict__ dst2, int ld2, int off2)
{
    int b = blockIdx.y;
    int h = blockIdx.x * blockDim.x + threadIdx.x;
    const float* wb = w + b * T;
    float a = 0.f;
    for (int t = 0; t < T; t++)
        a = fmaf(wb[t], enc[((size_t)t * BATCH + b) * HDIM + h], a);
    dst1[(size_t)b * ld1 + off1 + h] = a;
    if (dst2) dst2[(size_t)b * ld2 + off2 + h] = a;
}

__device__ __forceinline__ float sigf(float x) { return 1.f / (1.f + expf(-x)); }

__global__ void lstm_cell(const float* __restrict__ gates,
                          const float* __restrict__ cprev,
                          float* __restrict__ hout, float* __restrict__ cout,
                          float* __restrict__ hout2)   // optional, ld=2048 off=0
{
    int idx = blockIdx.x * blockDim.x + threadIdx.x;  // B*H
    int b = idx >> 10, h = idx & 1023;
    const float* g = gates + b * 4096;
    float i  = sigf(g[h]);
    float f  = sigf(g[1024 + h]);
    float gg = tanhf(g[2048 + h]);
    float o  = sigf(g[3072 + h]);
    float c  = f * cprev[idx] + i * gg;
    float hh = o * tanhf(c);
    hout[idx] = hh;
    cout[idx] = c;
    if (hout2) hout2[b * 2048 + h] = hh;
}

__global__ void logsoftmax_rows(float* __restrict__ x)
{
    __shared__ float sh[512];
    int b = blockIdx.x, tid = threadIdx.x;            // 512 threads
    float* row = x + (size_t)b * VDIM;

    float mx = -1e30f;
    for (int i = tid; i < VDIM; i += 512) mx = fmaxf(mx, row[i]);
    sh[tid] = mx; __syncthreads();
    for (int s = 256; s > 0; s >>= 1) { if (tid < s) sh[tid] = fmaxf(sh[tid], sh[tid + s]); __syncthreads(); }
    mx = sh[0]; __syncthreads();

    float sum = 0.f;
    for (int i = tid; i < VDIM; i += 512) sum += expf(row[i] - mx);
    sh[tid] = sum; __syncthreads();
    for (int s = 256; s > 0; s >>= 1) { if (tid < s) sh[tid] += sh[tid + s]; __syncthreads(); }
    float lse = mx + logf(sh[0]);

    for (int i = tid; i < VDIM; i += 512) row[i] -= lse;
}

// ---------------------------------------------------------------------------
// Launcher
// ---------------------------------------------------------------------------
extern "C" void kernel_launch(void* const* d_in, const int* in_sizes, int n_in,
                              void* d_out, int out_size)
{
    (void)in_sizes; (void)n_in; (void)out_size;
    const int*   input = (const int*)  d_in[0];
    const float* h0    = (const float*)d_in[1];
    const float* c0    = (const float*)d_in[2];
    const float* dh0   = (const float*)d_in[3];
    const float* dc0   = (const float*)d_in[4];
    const float* qo    = (const float*)d_in[5];
    const float* enc   = (const float*)d_in[6];
    const float* embed = (const float*)d_in[7];
    const float* W_qa  = (const float*)d_in[8];
    const float* b_qa  = (const float*)d_in[9];
    const float* v_q   = (const float*)d_in[10];
    const float* W_da  = (const float*)d_in[11];
    const float* b_da  = (const float*)d_in[12];
    const float* v_d   = (const float*)d_in[13];
    const float* W_ih  = (const float*)d_in[14];
    const float* W_hh  = (const float*)d_in[15];
    const float* b_ih  = (const float*)d_in[16];
    const float* b_hh  = (const float*)d_in[17];
    const float* Wd_ih = (const float*)d_in[18];
    const float* Wd_hh = (const float*)d_in[19];
    const float* bd_ih = (const float*)d_in[20];
    const float* bd_hh = (const float*)d_in[21];
    const float* W_out = (const float*)d_in[22];
    const float* b_out = (const float*)d_in[23];
    float* out = (float*)d_out;

    float *qpart, *partq, *wq, *docq, *dqpart, *partd, *wd, *xcat, *xout, *gates, *dgates;
    cudaGetSymbolAddress((void**)&qpart,  g_qpart);
    cudaGetSymbolAddress((void**)&partq,  g_partq);
    cudaGetSymbolAddress((void**)&wq,     g_wq);
    cudaGetSymbolAddress((void**)&docq,   g_docq);
    cudaGetSymbolAddress((void**)&dqpart, g_dqpart);
    cudaGetSymbolAddress((void**)&partd,  g_partd);
    cudaGetSymbolAddress((void**)&wd,     g_wd);
    cudaGetSymbolAddress((void**)&xcat,   g_xcat);
    cudaGetSymbolAddress((void**)&xout,   g_xout);
    cudaGetSymbolAddress((void**)&gates,  g_gates);
    cudaGetSymbolAddress((void**)&dgates, g_dgates);

    // Embedding gather into xcat[:, 0:512]; docq[:, 0:1024] = h_last
    gather_embed<<<BATCH, 512>>>(input, embed, xcat);
    copy_hlast  <<<BATCH, 1024>>>(h0, docq);

    // ---- Query attention ----
    // qpart = h_last @ W_qa[:, :H]^T
    gemm_nt<64,128,16,4,8,false><<<dim3(8,1),256>>>(
        h0, HDIM, W_qa, 2*HDIM, qpart, HDIM, BATCH, HDIM, HDIM,
        nullptr, nullptr, 0, nullptr, nullptr, nullptr);
    // fused energy + score partials over query_outputs
    gemm_nt<128,128,16,8,8,true><<<dim3(8, LQ*BATCH/128),256>>>(
        qo, HDIM, W_qa + HDIM, 2*HDIM, nullptr, 0, LQ*BATCH, HDIM, HDIM,
        b_qa, nullptr, 0, qpart, v_q, partq);
    qsoftmax<<<BATCH, 32>>>(partq, wq);
    weighted_ctx<<<dim3(HDIM/256, BATCH), 256>>>(wq, LQ, qo,
        docq, 2048, 1024, nullptr, 0, 0);

    // ---- Doc attention ----
    // dqpart = [h_last | q_ctx] @ W_da[:, :2H]^T
    gemm_nt<64,128,16,4,8,false><<<dim3(8,1),256>>>(
        docq, 2048, W_da, 3*HDIM, dqpart, HDIM, BATCH, HDIM, 2*HDIM,
        nullptr, nullptr, 0, nullptr, nullptr, nullptr);
    gemm_nt<128,128,16,8,8,true><<<dim3(8, LD*BATCH/128),256>>>(
        enc, HDIM, W_da + 2*HDIM, 3*HDIM, nullptr, 0, LD*BATCH, HDIM, HDIM,
        b_da, nullptr, 0, dqpart, v_d, partd);
    dsoftmax<<<BATCH, 256>>>(partd, wd, out + OFF_DOCW);
    weighted_ctx<<<dim3(HDIM/256, BATCH), 256>>>(wd, LD, enc,
        xcat, 1536, 512, xout, 2048, 1024);

    // ---- Distraction LSTM: dgates = doc_ctx@Wd_ih^T + dh0@Wd_hh^T + biases ----
    gemm_nt<64,128,16,4,8,false><<<dim3(32,1),256>>>(
        xcat + 512, 1536, Wd_ih, HDIM, dgates, 4096, BATCH, 4096, HDIM,
        nullptr, nullptr, 0, nullptr, nullptr, nullptr);
    gemm_nt<64,128,16,4,8,false><<<dim3(32,1),256>>>(
        dh0, HDIM, Wd_hh, HDIM, dgates, 4096, BATCH, 4096, HDIM,
        bd_ih, bd_hh, 1, nullptr, nullptr, nullptr);
    lstm_cell<<<BATCH*HDIM/256, 256>>>(dgates, dc0, out + OFF_DH, out + OFF_DC, nullptr);

    // ---- Main LSTM: gates = [emb|doc_ctx]@W_ih^T + h0@W_hh^T + biases ----
    gemm_nt<64,128,16,4,8,false><<<dim3(32,1),256>>>(
        xcat, 1536, W_ih, 1536, gates, 4096, BATCH, 4096, 1536,
        nullptr, nullptr, 0, nullptr, nullptr, nullptr);
    gemm_nt<64,128,16,4,8,false><<<dim3(32,1),256>>>(
        h0, HDIM, W_hh, HDIM, gates, 4096, BATCH, 4096, HDIM,
        b_ih, b_hh, 1, nullptr, nullptr, nullptr);
    lstm_cell<<<BATCH*HDIM/256, 256>>>(gates, c0, out + OFF_H1, out + OFF_C1, xout);

    // ---- Output projection + log_softmax ----
    gemm_nt<64,128,16,4,8,false><<<dim3((VDIM+127)/128, 1),256>>>(
        xout, 2048, W_out, 2048, out, VDIM, BATCH, VDIM, 2048,
        b_out, nullptr, 0, nullptr, nullptr, nullptr);
    logsoftmax_rows<<<BATCH, 512>>>(out);
}

// round 13
// speedup vs baseline: 3.3623x; 3.3616x over previous
#include <cuda_runtime.h>
#include <cstdint>
#include <math.h>

// ---------------------------------------------------------------------------
// Problem constants
// ---------------------------------------------------------------------------
#define BATCH 64
#define HDIM  1024
#define EDIM  512
#define VDIM  50000
#define LQ    32
#define LD    400

// Output layout (tuple concat, float32)
#define OFF_OUT   0
#define OFF_H1    (3200000)
#define OFF_C1    (OFF_H1 + 65536)
#define OFF_DH    (OFF_C1 + 65536)
#define OFF_DC    (OFF_DH + 65536)
#define OFF_DOCW  (OFF_DC + 65536)

#define PARTW 16   // score partials per row: 8 n-blocks x 2 n-warps

// ---------------------------------------------------------------------------
// Scratch (device globals: no allocations allowed)
// ---------------------------------------------------------------------------
__device__ float g_qpart [HDIM * BATCH];            // qpartT[e,b]
__device__ float g_partq [LQ * BATCH * PARTW];
__device__ float g_wq    [BATCH * LQ];
__device__ float g_docq  [BATCH * 2 * HDIM];        // [h_last | q_ctx]
__device__ float g_dqpart[HDIM * BATCH];            // dqpartT[e,b]
__device__ float g_partd [LD * BATCH * PARTW];
__device__ float g_wd    [BATCH * LD];
__device__ float g_xcat  [BATCH * 1536];            // [embedded(512) | doc_ctx(1024)]
__device__ float g_xout  [BATCH * 2048];            // [h1 | doc_ctx]
__device__ float g_gates [4096 * BATCH];            // gatesT[g,b]
__device__ float g_dgates[4096 * BATCH];            // dgatesT[g,b]

// ---------------------------------------------------------------------------
// PTX helpers (portable: cp.async + mma.sync, no sm_103a-only features)
// ---------------------------------------------------------------------------
__device__ __forceinline__ uint32_t smem_u32_of(const void* p) {
    uint32_t a;
    asm("{ .reg .u64 t; cvta.to.shared.u64 t, %1; cvt.u32.u64 %0, t; }" : "=r"(a) : "l"(p));
    return a;
}

__device__ __forceinline__ void cp_async16(uint32_t dst, const void* src, uint32_t sz) {
    asm volatile("cp.async.cg.shared.global [%0], [%1], 16, %2;"
                 :: "r"(dst), "l"(src), "r"(sz) : "memory");
}

__device__ __forceinline__ uint32_t f2tf32(float x) {
    uint32_t r;
    asm("cvt.rna.tf32.f32 %0, %1;" : "=r"(r) : "f"(x));
    return r;
}

// D(16x8) += A(16x8 tf32, row) * B(8x8 tf32, col)
__device__ __forceinline__ void mma_tf32(float* c, const uint32_t* a, const uint32_t* b) {
    asm volatile(
        "mma.sync.aligned.m16n8k8.row.col.f32.tf32.tf32.f32 "
        "{%0,%1,%2,%3}, {%4,%5,%6,%7}, {%8,%9}, {%0,%1,%2,%3};"
        : "+f"(c[0]), "+f"(c[1]), "+f"(c[2]), "+f"(c[3])
        : "r"(a[0]), "r"(a[1]), "r"(a[2]), "r"(a[3]), "r"(b[0]), "r"(b[1]));
}

// ---------------------------------------------------------------------------
// tf32 mma.sync GEMM:  C[M, N] = sum_pairs A_p[M, K_p] * B_p[N, K_p]^T
// BM=128, BK=32, 256 threads = 8 warps (4 in M x 2 in N), warp tile 32 x BN/2.
// Double-buffered cp.async stages; smem rows have stride 36 floats
// (16B-aligned, conflict-free fragment loads).
// EPI 0: dst[m*ldc + n] = acc + bias1[m] + bias2[m]
// EPI 1: dst[n*ldc + m] = acc + bias1[m]            (transposed store)
// EPI 2: part[m*PARTW + bx*2 + wn] = sum_n tanh(acc + qadd[n*64+(m&63)] + bias1[n]) * v[n]
// ---------------------------------------------------------------------------
template<int BN, int EPI>
__global__ __launch_bounds__(256)
void mma_gemm(const float* __restrict__ A1, int lda1, int K1,
              const float* __restrict__ B1, int ldb1,
              const float* __restrict__ A2, int lda2, int K2,
              const float* __restrict__ B2, int ldb2,
              int M,
              float* __restrict__ dst, int ldc,
              const float* __restrict__ bias1, const float* __restrict__ bias2,
              const float* __restrict__ qadd, const float* __restrict__ vvec,
              float* __restrict__ part)
{
    constexpr int WN  = BN / 2;
    constexpr int NT  = WN / 8;
    constexpr int AST = 36;                       // smem row stride (floats)
    constexpr int SF  = 128 * AST + BN * AST;     // floats per stage

    extern __shared__ float smem[];
    const uint32_t smem_addr = smem_u32_of(smem);

    const int tid  = threadIdx.x;
    const int w    = tid >> 5;
    const int lane = tid & 31;
    const int g    = lane >> 2;                   // groupID
    const int t    = lane & 3;                    // threadID_in_group
    const int wm0  = (w & 3) * 32;
    const int wnid = w >> 2;
    const int wn0  = wnid * WN;
    const int m0   = blockIdx.y * 128;
    const int n0   = blockIdx.x * BN;

    const int nk1 = K1 >> 5;
    const int nk  = nk1 + (K2 >> 5);

    float acc[2][NT][4];
#pragma unroll
    for (int mt = 0; mt < 2; mt++)
#pragma unroll
        for (int nt = 0; nt < NT; nt++)
#pragma unroll
            for (int j = 0; j < 4; j++) acc[mt][nt][j] = 0.f;

    auto load_chunk = [&](int stage, int c) {
        const float* Ap; const float* Bp; int lda, ldb, koff;
        if (c < nk1) { Ap = A1; Bp = B1; lda = lda1; ldb = ldb1; koff = c * 32; }
        else         { Ap = A2; Bp = B2; lda = lda2; ldb = ldb2; koff = (c - nk1) * 32; }
        const uint32_t sa = smem_addr + stage * SF * 4;
        const uint32_t sb = sa + 128 * AST * 4;
#pragma unroll
        for (int i = 0; i < 4; i++) {             // A: 128 rows x 32 floats
            int seg = i * 256 + tid;
            int row = seg >> 3, c4 = (seg & 7) * 4;
            int gr  = m0 + row;
            int grc = gr < M ? gr : (M - 1);      // clamp (size=0 below disables)
            cp_async16(sa + (uint32_t)(row * AST + c4) * 4,
                       Ap + (size_t)grc * lda + koff + c4,
                       gr < M ? 16u : 0u);
        }
#pragma unroll
        for (int i = 0; i < BN / 32; i++) {       // B: BN rows x 32 floats
            int seg = i * 256 + tid;
            int row = seg >> 3, c4 = (seg & 7) * 4;
            cp_async16(sb + (uint32_t)(row * AST + c4) * 4,
                       Bp + (size_t)(n0 + row) * ldb + koff + c4, 16u);
        }
        asm volatile("cp.async.commit_group;" ::: "memory");
    };

    load_chunk(0, 0);

#pragma unroll 1
    for (int c = 0; c < nk; c++) {
        const int s = c & 1;
        if (c + 1 < nk) {
            load_chunk(s ^ 1, c + 1);
            asm volatile("cp.async.wait_group 1;" ::: "memory");
        } else {
            asm volatile("cp.async.wait_group 0;" ::: "memory");
        }
        __syncthreads();

        const float* sA = smem + s * SF;
        const float* sB = sA + 128 * AST;

#pragma unroll
        for (int kk = 0; kk < 4; kk++) {
            const int kb = kk * 8;
            uint32_t ar[2][4];
#pragma unroll
            for (int mt = 0; mt < 2; mt++) {
                const int r = wm0 + mt * 16 + g;
                ar[mt][0] = f2tf32(sA[(r)     * AST + kb + t]);
                ar[mt][1] = f2tf32(sA[(r + 8) * AST + kb + t]);
                ar[mt][2] = f2tf32(sA[(r)     * AST + kb + t + 4]);
                ar[mt][3] = f2tf32(sA[(r + 8) * AST + kb + t + 4]);
            }
            uint32_t br[NT][2];
#pragma unroll
            for (int nt = 0; nt < NT; nt++) {
                const int r = wn0 + nt * 8 + g;
                br[nt][0] = f2tf32(sB[r * AST + kb + t]);
                br[nt][1] = f2tf32(sB[r * AST + kb + t + 4]);
            }
#pragma unroll
            for (int mt = 0; mt < 2; mt++)
#pragma unroll
                for (int nt = 0; nt < NT; nt++)
                    mma_tf32(acc[mt][nt], ar[mt], br[nt]);
        }
        __syncthreads();
    }

    // ---- Epilogue ----
    if constexpr (EPI == 2) {
#pragma unroll
        for (int mt = 0; mt < 2; mt++)
#pragma unroll
            for (int rh = 0; rh < 2; rh++) {
                const int m = m0 + wm0 + mt * 16 + g + rh * 8;
                const int b = m & (BATCH - 1);
                float p = 0.f;
#pragma unroll
                for (int nt = 0; nt < NT; nt++)
#pragma unroll
                    for (int cj = 0; cj < 2; cj++) {
                        const int n = n0 + wn0 + nt * 8 + 2 * t + cj;
                        float e = tanhf(acc[mt][nt][rh * 2 + cj]
                                        + qadd[n * BATCH + b] + bias1[n]);
                        p = fmaf(e, vvec[n], p);
                    }
                p += __shfl_xor_sync(0xffffffffu, p, 1);
                p += __shfl_xor_sync(0xffffffffu, p, 2);
                if (t == 0 && m < M)
                    part[(size_t)m * PARTW + blockIdx.x * 2 + wnid] = p;
            }
    } else {
#pragma unroll
        for (int mt = 0; mt < 2; mt++)
#pragma unroll
            for (int rh = 0; rh < 2; rh++) {
                const int m = m0 + wm0 + mt * 16 + g + rh * 8;
                if (m >= M) continue;
                float bb = 0.f;
                if (bias1) bb += bias1[m];
                if (EPI == 0 && bias2) bb += bias2[m];
#pragma unroll
                for (int nt = 0; nt < NT; nt++) {
                    const int n = n0 + wn0 + nt * 8 + 2 * t;
                    const float v0 = acc[mt][nt][rh * 2 + 0] + bb;
                    const float v1 = acc[mt][nt][rh * 2 + 1] + bb;
                    if constexpr (EPI == 0) {
                        dst[(size_t)m * ldc + n]     = v0;
                        dst[(size_t)m * ldc + n + 1] = v1;
                    } else {
                        dst[(size_t)(n)     * ldc + m] = v0;
                        dst[(size_t)(n + 1) * ldc + m] = v1;
                    }
                }
            }
    }
}

// ---------------------------------------------------------------------------
// Small helper kernels
// ---------------------------------------------------------------------------
__global__ void gather_embed(const int* __restrict__ idx,
                             const float* __restrict__ embed,
                             float* __restrict__ xcat)
{
    int b = blockIdx.x, e = threadIdx.x;              // 512 threads
    xcat[b * 1536 + e] = embed[(size_t)idx[b] * EDIM + e];
}

__global__ void copy_hlast(const float* __restrict__ h0, float* __restrict__ docq)
{
    int b = blockIdx.x, h = threadIdx.x;              // 1024 threads
    docq[b * 2048 + h] = h0[b * HDIM + h];
}

__device__ __forceinline__ float sum_part(const float* __restrict__ p) {
    float s = 0.f;
#pragma unroll
    for (int i = 0; i < PARTW; i++) s += p[i];
    return s;
}

__global__ void qsoftmax(const float* __restrict__ part, float* __restrict__ w)
{
    int b = blockIdx.x, t = threadIdx.x;              // 32 threads
    float s = sum_part(part + ((size_t)t * BATCH + b) * PARTW);
    float mx = s;
#pragma unroll
    for (int o = 16; o; o >>= 1) mx = fmaxf(mx, __shfl_xor_sync(0xffffffffu, mx, o));
    float e = expf(s - mx);
    float sum = e;
#pragma unroll
    for (int o = 16; o; o >>= 1) sum += __shfl_xor_sync(0xffffffffu, sum, o);
    w[b * LQ + t] = e / sum;
}

__global__ void dsoftmax(const float* __restrict__ part,
                         float* __restrict__ w, float* __restrict__ outw)
{
    __shared__ float sh[256];
    int b = blockIdx.x, tid = threadIdx.x;            // 256 threads
    float mx = -1e30f;
    for (int t = tid; t < LD; t += 256)
        mx = fmaxf(mx, sum_part(part + ((size_t)t * BATCH + b) * PARTW));
    sh[tid] = mx; __syncthreads();
    for (int s = 128; s > 0; s >>= 1) { if (tid < s) sh[tid] = fmaxf(sh[tid], sh[tid + s]); __syncthreads(); }
    mx = sh[0]; __syncthreads();

    float sum = 0.f;
    for (int t = tid; t < LD; t += 256)
        sum += expf(sum_part(part + ((size_t)t * BATCH + b) * PARTW) - mx);
    sh[tid] = sum; __syncthreads();
    for (int s = 128; s > 0; s >>= 1) { if (tid < s) sh[tid] += sh[tid + s]; __syncthreads(); }
    float tot = sh[0];

    for (int t = tid; t < LD; t += 256) {
        float s = sum_part(part + ((size_t)t * BATCH + b) * PARTW);
        float v = expf(s - mx) / tot;
        w[b * LD + t]    = v;
        outw[b * LD + t] = v;
    }
}

__global__ void weighted_ctx(const float* __restrict__ w, int T,
                             const float* __restrict__ enc,
                             float* __restrict__ dst1, int ld1, int off1,
                             float* __restrict__ dst2, int ld2, int off2)
{
    int b = blockIdx.y;
    int h = blockIdx.x * blockDim.x + threadIdx.x;
    const float* wb = w + b * T;
    float a = 0.f;
    for (int t = 0; t < T; t++)
        a = fmaf(wb[t], enc[((size_t)t * BATCH + b) * HDIM + h], a);
    dst1[(size_t)b * ld1 + off1 + h] = a;
    if (dst2) dst2[(size_t)b * ld2 + off2 + h] = a;
}

__device__ __forceinline__ float sigf(float x) { return 1.f / (1.f + expf(-x)); }

// gates stored transposed: gT[g * 64 + b]
__global__ void lstm_cell(const float* __restrict__ gT,
                          const float* __restrict__ cprev,
                          float* __restrict__ hout, float* __restrict__ cout,
                          float* __restrict__ hout2)
{
    int idx = blockIdx.x * blockDim.x + threadIdx.x;  // B*H, b fastest
    int b = idx & 63, h = idx >> 6;
    float i  = sigf (gT[(h)        * BATCH + b]);
    float f  = sigf (gT[(1024 + h) * BATCH + b]);
    float gg = tanhf(gT[(2048 + h) * BATCH + b]);
    float o  = sigf (gT[(3072 + h) * BATCH + b]);
    float c  = f * cprev[b * HDIM + h] + i * gg;
    float hh = o * tanhf(c);
    hout[b * HDIM + h] = hh;
    cout[b * HDIM + h] = c;
    if (hout2) hout2[b * 2048 + h] = hh;
}

__global__ void logsoftmax_rows(float* __restrict__ x)
{
    __shared__ float sh[1024];
    int b = blockIdx.x, tid = threadIdx.x;            // 1024 threads
    float* row = x + (size_t)b * VDIM;

    float mx = -1e30f;
    for (int i = tid; i < VDIM; i += 1024) mx = fmaxf(mx, row[i]);
    sh[tid] = mx; __syncthreads();
    for (int s = 512; s > 0; s >>= 1) { if (tid < s) sh[tid] = fmaxf(sh[tid], sh[tid + s]); __syncthreads(); }
    mx = sh[0]; __syncthreads();

    float sum = 0.f;
    for (int i = tid; i < VDIM; i += 1024) sum += expf(row[i] - mx);
    sh[tid] = sum; __syncthreads();
    for (int s = 512; s > 0; s >>= 1) { if (tid < s) sh[tid] += sh[tid + s]; __syncthreads(); }
    float lse = mx + logf(sh[0]);

    for (int i = tid; i < VDIM; i += 1024) row[i] -= lse;
}

// ---------------------------------------------------------------------------
// Launcher
// ---------------------------------------------------------------------------
extern "C" void kernel_launch(void* const* d_in, const int* in_sizes, int n_in,
                              void* d_out, int out_size)
{
    (void)in_sizes; (void)n_in; (void)out_size;
    const int*   input = (const int*)  d_in[0];
    const float* h0    = (const float*)d_in[1];
    const float* c0    = (const float*)d_in[2];
    const float* dh0   = (const float*)d_in[3];
    const float* dc0   = (const float*)d_in[4];
    const float* qo    = (const float*)d_in[5];
    const float* enc   = (const float*)d_in[6];
    const float* embed = (const float*)d_in[7];
    const float* W_qa  = (const float*)d_in[8];
    const float* b_qa  = (const float*)d_in[9];
    const float* v_q   = (const float*)d_in[10];
    const float* W_da  = (const float*)d_in[11];
    const float* b_da  = (const float*)d_in[12];
    const float* v_d   = (const float*)d_in[13];
    const float* W_ih  = (const float*)d_in[14];
    const float* W_hh  = (const float*)d_in[15];
    const float* b_ih  = (const float*)d_in[16];
    const float* b_hh  = (const float*)d_in[17];
    const float* Wd_ih = (const float*)d_in[18];
    const float* Wd_hh = (const float*)d_in[19];
    const float* bd_ih = (const float*)d_in[20];
    const float* bd_hh = (const float*)d_in[21];
    const float* W_out = (const float*)d_in[22];
    const float* b_out = (const float*)d_in[23];
    float* out = (float*)d_out;

    float *qpartT, *partq, *wq, *docq, *dqpartT, *partd, *wd, *xcat, *xout, *gatesT, *dgatesT;
    cudaGetSymbolAddress((void**)&qpartT,  g_qpart);
    cudaGetSymbolAddress((void**)&partq,   g_partq);
    cudaGetSymbolAddress((void**)&wq,      g_wq);
    cudaGetSymbolAddress((void**)&docq,    g_docq);
    cudaGetSymbolAddress((void**)&dqpartT, g_dqpart);
    cudaGetSymbolAddress((void**)&partd,   g_partd);
    cudaGetSymbolAddress((void**)&wd,      g_wd);
    cudaGetSymbolAddress((void**)&xcat,    g_xcat);
    cudaGetSymbolAddress((void**)&xout,    g_xout);
    cudaGetSymbolAddress((void**)&gatesT,  g_gates);
    cudaGetSymbolAddress((void**)&dgatesT, g_dgates);

    // smem: 2 stages * (128 + BN) rows * 36 floats * 4 B
    const int SM128 = 2 * (128 + 128) * 36 * 4;   // 73728
    const int SM64  = 2 * (128 +  64) * 36 * 4;   // 55296
    cudaFuncSetAttribute(mma_gemm<128, 2>, cudaFuncAttributeMaxDynamicSharedMemorySize, SM128);
    cudaFuncSetAttribute(mma_gemm<64, 0>,  cudaFuncAttributeMaxDynamicSharedMemorySize, SM64);
    cudaFuncSetAttribute(mma_gemm<64, 1>,  cudaFuncAttributeMaxDynamicSharedMemorySize, SM64);

    gather_embed<<<BATCH, 512>>>(input, embed, xcat);
    copy_hlast  <<<BATCH, 1024>>>(h0, docq);

    // ---- Query attention ----
    // qpartT[e,b] = sum_k W_qa[e,k] * h0[b,k]
    mma_gemm<64, 0><<<dim3(1, 8), 256, SM64>>>(
        W_qa, 2 * HDIM, HDIM, h0, HDIM,
        nullptr, 0, 0, nullptr, 0,
        HDIM, qpartT, BATCH, nullptr, nullptr, nullptr, nullptr, nullptr);
    // fused energy + per-(row, nblk) score partials over query_outputs
    mma_gemm<128, 2><<<dim3(8, 16), 256, SM128>>>(
        qo, HDIM, HDIM, W_qa + HDIM, 2 * HDIM,
        nullptr, 0, 0, nullptr, 0,
        LQ * BATCH, nullptr, 0, b_qa, nullptr, qpartT, v_q, partq);
    qsoftmax<<<BATCH, 32>>>(partq, wq);
    weighted_ctx<<<dim3(HDIM / 256, BATCH), 256>>>(wq, LQ, qo,
        docq, 2048, 1024, nullptr, 0, 0);

    // ---- Doc attention ----
    mma_gemm<64, 0><<<dim3(1, 8), 256, SM64>>>(
        W_da, 3 * HDIM, 2 * HDIM, docq, 2 * HDIM,
        nullptr, 0, 0, nullptr, 0,
        HDIM, dqpartT, BATCH, nullptr, nullptr, nullptr, nullptr, nullptr);
    mma_gemm<128, 2><<<dim3(8, 200), 256, SM128>>>(
        enc, HDIM, HDIM, W_da + 2 * HDIM, 3 * HDIM,
        nullptr, 0, 0, nullptr, 0,
        LD * BATCH, nullptr, 0, b_da, nullptr, dqpartT, v_d, partd);
    dsoftmax<<<BATCH, 256>>>(partd, wd, out + OFF_DOCW);
    weighted_ctx<<<dim3(HDIM / 256, BATCH), 256>>>(wd, LD, enc,
        xcat, 1536, 512, xout, 2048, 1024);

    // ---- Distraction LSTM: dgatesT = Wd_ih@doc_ctx^T + Wd_hh@dh0^T + biases ----
    mma_gemm<64, 0><<<dim3(1, 32), 256, SM64>>>(
        Wd_ih, HDIM, HDIM, xcat + 512, 1536,
        Wd_hh, HDIM, HDIM, dh0, HDIM,
        4 * HDIM, dgatesT, BATCH, bd_ih, bd_hh, nullptr, nullptr, nullptr);
    lstm_cell<<<BATCH * HDIM / 256, 256>>>(dgatesT, dc0, out + OFF_DH, out + OFF_DC, nullptr);

    // ---- Main LSTM: gatesT = W_ih@[emb|doc_ctx]^T + W_hh@h0^T + biases ----
    mma_gemm<64, 0><<<dim3(1, 32), 256, SM64>>>(
        W_ih, 1536, 1536, xcat, 1536,
        W_hh, HDIM, HDIM, h0, HDIM,
        4 * HDIM, gatesT, BATCH, b_ih, b_hh, nullptr, nullptr, nullptr);
    lstm_cell<<<BATCH * HDIM / 256, 256>>>(gatesT, c0, out + OFF_H1, out + OFF_C1, xout);

    // ---- Output projection (as out^T: M=V rows, N=64) + log_softmax ----
    mma_gemm<64, 1><<<dim3(1, (VDIM + 127) / 128), 256, SM64>>>(
        W_out, 2 * HDIM, 2 * HDIM, xout, 2 * HDIM,
        nullptr, 0, 0, nullptr, 0,
        VDIM, out, VDIM, b_out, nullptr, nullptr, nullptr, nullptr);
    logsoftmax_rows<<<BATCH, 1024>>>(out);
}

// round 14
// speedup vs baseline: 3.7515x; 1.1158x over previous
#include <cuda_runtime.h>
#include <cstdint>
#include <math.h>

// ---------------------------------------------------------------------------
// Problem constants
// ---------------------------------------------------------------------------
#define BATCH 64
#define HDIM  1024
#define EDIM  512
#define VDIM  50000
#define LQ    32
#define LD    400

// Output layout (tuple concat, float32)
#define OFF_OUT   0
#define OFF_H1    (3200000)
#define OFF_C1    (OFF_H1 + 65536)
#define OFF_DH    (OFF_C1 + 65536)
#define OFF_DC    (OFF_DH + 65536)
#define OFF_DOCW  (OFF_DC + 65536)

#define PARTW 16   // score partials per row: 4 n-blocks x 4 n-warps

// ---------------------------------------------------------------------------
// Scratch (device globals: no allocations allowed)
// ---------------------------------------------------------------------------
__device__ float g_qpart [HDIM * BATCH];            // qpartT[e,b]
__device__ float g_partq [LQ * BATCH * PARTW];
__device__ float g_wq    [BATCH * LQ];
__device__ float g_docq  [BATCH * 2 * HDIM];        // [h_last | q_ctx]
__device__ float g_dqpart[HDIM * BATCH];            // dqpartT[e,b]
__device__ float g_partd [LD * BATCH * PARTW];
__device__ float g_wd    [BATCH * LD];
__device__ float g_xcat  [BATCH * 1536];            // [embedded(512) | doc_ctx(1024)]
__device__ float g_xout  [BATCH * 2048];            // [h1 | doc_ctx]
__device__ float g_gates [4096 * BATCH];            // gatesT[g,b]
__device__ float g_dgates[4096 * BATCH];            // dgatesT[g,b]

// ---------------------------------------------------------------------------
// PTX helpers (portable: cp.async + mma.sync)
// ---------------------------------------------------------------------------
__device__ __forceinline__ uint32_t smem_u32_of(const void* p) {
    uint32_t a;
    asm("{ .reg .u64 t; cvta.to.shared.u64 t, %1; cvt.u32.u64 %0, t; }" : "=r"(a) : "l"(p));
    return a;
}

__device__ __forceinline__ void cp_async16(uint32_t dst, const void* src, uint32_t sz) {
    asm volatile("cp.async.cg.shared.global [%0], [%1], 16, %2;"
                 :: "r"(dst), "l"(src), "r"(sz) : "memory");
}

// D(16x8) += A(16x8 tf32, row) * B(8x8 tf32, col)
// Raw fp32 bits are passed: HW ignores the low 13 mantissa bits of tf32 operands.
__device__ __forceinline__ void mma_tf32(float* c, const uint32_t* a, const uint32_t* b) {
    asm volatile(
        "mma.sync.aligned.m16n8k8.row.col.f32.tf32.tf32.f32 "
        "{%0,%1,%2,%3}, {%4,%5,%6,%7}, {%8,%9}, {%0,%1,%2,%3};"
        : "+f"(c[0]), "+f"(c[1]), "+f"(c[2]), "+f"(c[3])
        : "r"(a[0]), "r"(a[1]), "r"(a[2]), "r"(a[3]), "r"(b[0]), "r"(b[1]));
}

// ---------------------------------------------------------------------------
// tf32 mma.sync GEMM:  C[M, N] = sum_pairs A_p[M, K_p] * B_p[N, K_p]^T
// BM=128, BK=32, 256 threads = 8 warps arranged (128/WM) x (BN/WN).
// Double-buffered cp.async stages; smem rows stride 36 floats (conflict-free).
// EPI 0: dst[m*ldc + n] = acc + bias1[m] + bias2[m]
// EPI 1: dst[n*ldc + m] = acc + bias1[m]            (transposed store)
// EPI 2: part[m*PARTW + bx*NW + wn] = sum_n tanh(acc + qadd[n*64+(m&63)] + bias1[n]) * v[n]
// ---------------------------------------------------------------------------
template<int BN, int WM, int WN, int EPI>
__global__ __launch_bounds__(256)
void mma_gemm(const float* __restrict__ A1, int lda1, int K1,
              const float* __restrict__ B1, int ldb1,
              const float* __restrict__ A2, int lda2, int K2,
              const float* __restrict__ B2, int ldb2,
              int M,
              float* __restrict__ dst, int ldc,
              const float* __restrict__ bias1, const float* __restrict__ bias2,
              const float* __restrict__ qadd, const float* __restrict__ vvec,
              float* __restrict__ part)
{
    constexpr int MW  = 128 / WM;                 // warps along M
    constexpr int NW  = BN / WN;                  // warps along N
    static_assert(MW * NW == 8, "8 warps");
    constexpr int MT  = WM / 16;                  // 16-row MMA tiles per warp
    constexpr int NT  = WN / 8;                   // 8-col MMA tiles per warp
    constexpr int AST = 36;                       // smem row stride (floats)
    constexpr int SF  = 128 * AST + BN * AST;     // floats per stage

    extern __shared__ float smem[];
    const uint32_t smem_addr = smem_u32_of(smem);

    const int tid  = threadIdx.x;
    const int w    = tid >> 5;
    const int lane = tid & 31;
    const int g    = lane >> 2;                   // groupID (row within 8)
    const int t    = lane & 3;                    // threadID_in_group
    const int wmid = w % MW;
    const int wnid = w / MW;
    const int wm0  = wmid * WM;
    const int wn0  = wnid * WN;
    const int m0   = blockIdx.y * 128;
    const int n0   = blockIdx.x * BN;

    const int nk1 = K1 >> 5;
    const int nk  = nk1 + (K2 >> 5);

    float acc[MT][NT][4];
#pragma unroll
    for (int mt = 0; mt < MT; mt++)
#pragma unroll
        for (int nt = 0; nt < NT; nt++)
#pragma unroll
            for (int j = 0; j < 4; j++) acc[mt][nt][j] = 0.f;

    auto load_chunk = [&](int stage, int c) {
        const float* Ap; const float* Bp; int lda, ldb, koff;
        if (c < nk1) { Ap = A1; Bp = B1; lda = lda1; ldb = ldb1; koff = c * 32; }
        else         { Ap = A2; Bp = B2; lda = lda2; ldb = ldb2; koff = (c - nk1) * 32; }
        const uint32_t sa = smem_addr + stage * SF * 4;
        const uint32_t sb = sa + 128 * AST * 4;
#pragma unroll
        for (int i = 0; i < 4; i++) {             // A: 128 rows x 32 floats
            int seg = i * 256 + tid;
            int row = seg >> 3, c4 = (seg & 7) * 4;
            int gr  = m0 + row;
            int grc = gr < M ? gr : (M - 1);
            cp_async16(sa + (uint32_t)(row * AST + c4) * 4,
                       Ap + (size_t)grc * lda + koff + c4,
                       gr < M ? 16u : 0u);
        }
#pragma unroll
        for (int i = 0; i < BN / 32; i++) {       // B: BN rows x 32 floats
            int seg = i * 256 + tid;
            int row = seg >> 3, c4 = (seg & 7) * 4;
            cp_async16(sb + (uint32_t)(row * AST + c4) * 4,
                       Bp + (size_t)(n0 + row) * ldb + koff + c4, 16u);
        }
        asm volatile("cp.async.commit_group;" ::: "memory");
    };

    load_chunk(0, 0);

#pragma unroll 1
    for (int c = 0; c < nk; c++) {
        const int s = c & 1;
        if (c + 1 < nk) {
            load_chunk(s ^ 1, c + 1);
            asm volatile("cp.async.wait_group 1;" ::: "memory");
        } else {
            asm volatile("cp.async.wait_group 0;" ::: "memory");
        }
        __syncthreads();

        const float* sA = smem + s * SF;
        const float* sB = sA + 128 * AST;

#pragma unroll
        for (int kk = 0; kk < 4; kk++) {
            const int kb = kk * 8;
            uint32_t ar[MT][4];
#pragma unroll
            for (int mt = 0; mt < MT; mt++) {
                const int r = wm0 + mt * 16 + g;
                ar[mt][0] = __float_as_uint(sA[(r)     * AST + kb + t]);
                ar[mt][1] = __float_as_uint(sA[(r + 8) * AST + kb + t]);
                ar[mt][2] = __float_as_uint(sA[(r)     * AST + kb + t + 4]);
                ar[mt][3] = __float_as_uint(sA[(r + 8) * AST + kb + t + 4]);
            }
#pragma unroll
            for (int nt = 0; nt < NT; nt++) {
                uint32_t br[2];
                const int r = wn0 + nt * 8 + g;
                br[0] = __float_as_uint(sB[r * AST + kb + t]);
                br[1] = __float_as_uint(sB[r * AST + kb + t + 4]);
#pragma unroll
                for (int mt = 0; mt < MT; mt++)
                    mma_tf32(acc[mt][nt], ar[mt], br);
            }
        }
        __syncthreads();
    }

    // ---- Epilogue ----
    if constexpr (EPI == 2) {
#pragma unroll
        for (int mt = 0; mt < MT; mt++)
#pragma unroll
            for (int rh = 0; rh < 2; rh++) {
                const int m = m0 + wm0 + mt * 16 + g + rh * 8;
                const int b = m & (BATCH - 1);
                float p = 0.f;
#pragma unroll
                for (int nt = 0; nt < NT; nt++)
#pragma unroll
                    for (int cj = 0; cj < 2; cj++) {
                        const int n = n0 + wn0 + nt * 8 + 2 * t + cj;
                        float e = tanhf(acc[mt][nt][rh * 2 + cj]
                                        + qadd[n * BATCH + b] + bias1[n]);
                        p = fmaf(e, vvec[n], p);
                    }
                p += __shfl_xor_sync(0xffffffffu, p, 1);
                p += __shfl_xor_sync(0xffffffffu, p, 2);
                if (t == 0 && m < M)
                    part[(size_t)m * PARTW + blockIdx.x * NW + wnid] = p;
            }
    } else {
#pragma unroll
        for (int mt = 0; mt < MT; mt++)
#pragma unroll
            for (int rh = 0; rh < 2; rh++) {
                const int m = m0 + wm0 + mt * 16 + g + rh * 8;
                if (m >= M) continue;
                float bb = 0.f;
                if (bias1) bb += bias1[m];
                if (EPI == 0 && bias2) bb += bias2[m];
#pragma unroll
                for (int nt = 0; nt < NT; nt++) {
                    const int n = n0 + wn0 + nt * 8 + 2 * t;
                    const float v0 = acc[mt][nt][rh * 2 + 0] + bb;
                    const float v1 = acc[mt][nt][rh * 2 + 1] + bb;
                    if constexpr (EPI == 0) {
                        dst[(size_t)m * ldc + n]     = v0;
                        dst[(size_t)m * ldc + n + 1] = v1;
                    } else {
                        dst[(size_t)(n)     * ldc + m] = v0;
                        dst[(size_t)(n + 1) * ldc + m] = v1;
                    }
                }
            }
    }
}

// ---------------------------------------------------------------------------
// Small helper kernels
// ---------------------------------------------------------------------------
__global__ void gather_embed(const int* __restrict__ idx,
                             const float* __restrict__ embed,
                             float* __restrict__ xcat)
{
    int b = blockIdx.x, e = threadIdx.x;              // 512 threads
    xcat[b * 1536 + e] = embed[(size_t)idx[b] * EDIM + e];
}

__global__ void copy_hlast(const float* __restrict__ h0, float* __restrict__ docq)
{
    int b = blockIdx.x, h = threadIdx.x;              // 1024 threads
    docq[b * 2048 + h] = h0[b * HDIM + h];
}

__device__ __forceinline__ float sum_part(const float* __restrict__ p) {
    float s = 0.f;
#pragma unroll
    for (int i = 0; i < PARTW; i++) s += p[i];
    return s;
}

__global__ void qsoftmax(const float* __restrict__ part, float* __restrict__ w)
{
    int b = blockIdx.x, t = threadIdx.x;              // 32 threads
    float s = sum_part(part + ((size_t)t * BATCH + b) * PARTW);
    float mx = s;
#pragma unroll
    for (int o = 16; o; o >>= 1) mx = fmaxf(mx, __shfl_xor_sync(0xffffffffu, mx, o));
    float e = expf(s - mx);
    float sum = e;
#pragma unroll
    for (int o = 16; o; o >>= 1) sum += __shfl_xor_sync(0xffffffffu, sum, o);
    w[b * LQ + t] = e / sum;
}

__global__ void dsoftmax(const float* __restrict__ part,
                         float* __restrict__ w, float* __restrict__ outw)
{
    __shared__ float sh[256];
    int b = blockIdx.x, tid = threadIdx.x;            // 256 threads
    float mx = -1e30f;
    for (int t = tid; t < LD; t += 256)
        mx = fmaxf(mx, sum_part(part + ((size_t)t * BATCH + b) * PARTW));
    sh[tid] = mx; __syncthreads();
    for (int s = 128; s > 0; s >>= 1) { if (tid < s) sh[tid] = fmaxf(sh[tid], sh[tid + s]); __syncthreads(); }
    mx = sh[0]; __syncthreads();

    float sum = 0.f;
    for (int t = tid; t < LD; t += 256)
        sum += expf(sum_part(part + ((size_t)t * BATCH + b) * PARTW) - mx);
    sh[tid] = sum; __syncthreads();
    for (int s = 128; s > 0; s >>= 1) { if (tid < s) sh[tid] += sh[tid + s]; __syncthreads(); }
    float tot = sh[0];

    for (int t = tid; t < LD; t += 256) {
        float s = sum_part(part + ((size_t)t * BATCH + b) * PARTW);
        float v = expf(s - mx) / tot;
        w[b * LD + t]    = v;
        outw[b * LD + t] = v;
    }
}

__global__ void weighted_ctx(const float* __restrict__ w, int T,
                             const float* __restrict__ enc,
                             float* __restrict__ dst1, int ld1, int off1,
                             float* __restrict__ dst2, int ld2, int off2)
{
    int b = blockIdx.y;
    int h = blockIdx.x * blockDim.x + threadIdx.x;
    const float* wb = w + b * T;
    float a = 0.f;
    for (int t = 0; t < T; t++)
        a = fmaf(wb[t], enc[((size_t)t * BATCH + b) * HDIM + h], a);
    dst1[(size_t)b * ld1 + off1 + h] = a;
    if (dst2) dst2[(size_t)b * ld2 + off2 + h] = a;
}

__device__ __forceinline__ float sigf(float x) { return 1.f / (1.f + expf(-x)); }

// gates stored transposed: gT[g * 64 + b]
__global__ void lstm_cell(const float* __restrict__ gT,
                          const float* __restrict__ cprev,
                          float* __restrict__ hout, float* __restrict__ cout,
                          float* __restrict__ hout2)
{
    int idx = blockIdx.x * blockDim.x + threadIdx.x;  // B*H, b fastest
    int b = idx & 63, h = idx >> 6;
    float i  = sigf (gT[(h)        * BATCH + b]);
    float f  = sigf (gT[(1024 + h) * BATCH + b]);
    float gg = tanhf(gT[(2048 + h) * BATCH + b]);
    float o  = sigf (gT[(3072 + h) * BATCH + b]);
    float c  = f * cprev[b * HDIM + h] + i * gg;
    float hh = o * tanhf(c);
    hout[b * HDIM + h] = hh;
    cout[b * HDIM + h] = c;
    if (hout2) hout2[b * 2048 + h] = hh;
}

__global__ void logsoftmax_rows(float* __restrict__ x)
{
    __shared__ float sh[1024];
    int b = blockIdx.x, tid = threadIdx.x;            // 1024 threads
    float* row = x + (size_t)b * VDIM;

    float mx = -1e30f;
    for (int i = tid; i < VDIM; i += 1024) mx = fmaxf(mx, row[i]);
    sh[tid] = mx; __syncthreads();
    for (int s = 512; s > 0; s >>= 1) { if (tid < s) sh[tid] = fmaxf(sh[tid], sh[tid + s]); __syncthreads(); }
    mx = sh[0]; __syncthreads();

    float sum = 0.f;
    for (int i = tid; i < VDIM; i += 1024) sum += expf(row[i] - mx);
    sh[tid] = sum; __syncthreads();
    for (int s = 512; s > 0; s >>= 1) { if (tid < s) sh[tid] += sh[tid + s]; __syncthreads(); }
    float lse = mx + logf(sh[0]);

    for (int i = tid; i < VDIM; i += 1024) row[i] -= lse;
}

// ---------------------------------------------------------------------------
// Launcher
// ---------------------------------------------------------------------------
extern "C" void kernel_launch(void* const* d_in, const int* in_sizes, int n_in,
                              void* d_out, int out_size)
{
    (void)in_sizes; (void)n_in; (void)out_size;
    const int*   input = (const int*)  d_in[0];
    const float* h0    = (const float*)d_in[1];
    const float* c0    = (const float*)d_in[2];
    const float* dh0   = (const float*)d_in[3];
    const float* dc0   = (const float*)d_in[4];
    const float* qo    = (const float*)d_in[5];
    const float* enc   = (const float*)d_in[6];
    const float* embed = (const float*)d_in[7];
    const float* W_qa  = (const float*)d_in[8];
    const float* b_qa  = (const float*)d_in[9];
    const float* v_q   = (const float*)d_in[10];
    const float* W_da  = (const float*)d_in[11];
    const float* b_da  = (const float*)d_in[12];
    const float* v_d   = (const float*)d_in[13];
    const float* W_ih  = (const float*)d_in[14];
    const float* W_hh  = (const float*)d_in[15];
    const float* b_ih  = (const float*)d_in[16];
    const float* b_hh  = (const float*)d_in[17];
    const float* Wd_ih = (const float*)d_in[18];
    const float* Wd_hh = (const float*)d_in[19];
    const float* bd_ih = (const float*)d_in[20];
    const float* bd_hh = (const float*)d_in[21];
    const float* W_out = (const float*)d_in[22];
    const float* b_out = (const float*)d_in[23];
    float* out = (float*)d_out;

    float *qpartT, *partq, *wq, *docq, *dqpartT, *partd, *wd, *xcat, *xout, *gatesT, *dgatesT;
    cudaGetSymbolAddress((void**)&qpartT,  g_qpart);
    cudaGetSymbolAddress((void**)&partq,   g_partq);
    cudaGetSymbolAddress((void**)&wq,      g_wq);
    cudaGetSymbolAddress((void**)&docq,    g_docq);
    cudaGetSymbolAddress((void**)&dqpartT, g_dqpart);
    cudaGetSymbolAddress((void**)&partd,   g_partd);
    cudaGetSymbolAddress((void**)&wd,      g_wd);
    cudaGetSymbolAddress((void**)&xcat,    g_xcat);
    cudaGetSymbolAddress((void**)&xout,    g_xout);
    cudaGetSymbolAddress((void**)&gatesT,  g_gates);
    cudaGetSymbolAddress((void**)&dgatesT, g_dgates);

    // smem: 2 stages * (128 + BN) rows * 36 floats * 4 B
    const int SM256 = 2 * (128 + 256) * 36 * 4;   // 110592
    const int SM64  = 2 * (128 +  64) * 36 * 4;   //  55296
    cudaFuncSetAttribute((const void*)mma_gemm<256, 64, 64, 2>,
                         cudaFuncAttributeMaxDynamicSharedMemorySize, SM256);
    cudaFuncSetAttribute((const void*)mma_gemm<64, 32, 32, 0>,
                         cudaFuncAttributeMaxDynamicSharedMemorySize, SM64);
    cudaFuncSetAttribute((const void*)mma_gemm<64, 32, 32, 1>,
                         cudaFuncAttributeMaxDynamicSharedMemorySize, SM64);

    gather_embed<<<BATCH, 512>>>(input, embed, xcat);
    copy_hlast  <<<BATCH, 1024>>>(h0, docq);

    // ---- Query attention ----
    // qpartT[e,b] = sum_k W_qa[e,k] * h0[b,k]
    mma_gemm<64, 32, 32, 0><<<dim3(1, 8), 256, SM64>>>(
        W_qa, 2 * HDIM, HDIM, h0, HDIM,
        nullptr, 0, 0, nullptr, 0,
        HDIM, qpartT, BATCH, nullptr, nullptr, nullptr, nullptr, nullptr);
    // fused energy + per-(row, nblk, nwarp) score partials over query_outputs
    mma_gemm<256, 64, 64, 2><<<dim3(4, 16), 256, SM256>>>(
        qo, HDIM, HDIM, W_qa + HDIM, 2 * HDIM,
        nullptr, 0, 0, nullptr, 0,
        LQ * BATCH, nullptr, 0, b_qa, nullptr, qpartT, v_q, partq);
    qsoftmax<<<BATCH, 32>>>(partq, wq);
    weighted_ctx<<<dim3(HDIM / 256, BATCH), 256>>>(wq, LQ, qo,
        docq, 2048, 1024, nullptr, 0, 0);

    // ---- Doc attention ----
    mma_gemm<64, 32, 32, 0><<<dim3(1, 8), 256, SM64>>>(
        W_da, 3 * HDIM, 2 * HDIM, docq, 2 * HDIM,
        nullptr, 0, 0, nullptr, 0,
        HDIM, dqpartT, BATCH, nullptr, nullptr, nullptr, nullptr, nullptr);
    mma_gemm<256, 64, 64, 2><<<dim3(4, 200), 256, SM256>>>(
        enc, HDIM, HDIM, W_da + 2 * HDIM, 3 * HDIM,
        nullptr, 0, 0, nullptr, 0,
        LD * BATCH, nullptr, 0, b_da, nullptr, dqpartT, v_d, partd);
    dsoftmax<<<BATCH, 256>>>(partd, wd, out + OFF_DOCW);
    weighted_ctx<<<dim3(HDIM / 256, BATCH), 256>>>(wd, LD, enc,
        xcat, 1536, 512, xout, 2048, 1024);

    // ---- Distraction LSTM: dgatesT = Wd_ih@doc_ctx^T + Wd_hh@dh0^T + biases ----
    mma_gemm<64, 32, 32, 0><<<dim3(1, 32), 256, SM64>>>(
        Wd_ih, HDIM, HDIM, xcat + 512, 1536,
        Wd_hh, HDIM, HDIM, dh0, HDIM,
        4 * HDIM, dgatesT, BATCH, bd_ih, bd_hh, nullptr, nullptr, nullptr);
    lstm_cell<<<BATCH * HDIM / 256, 256>>>(dgatesT, dc0, out + OFF_DH, out + OFF_DC, nullptr);

    // ---- Main LSTM: gatesT = W_ih@[emb|doc_ctx]^T + W_hh@h0^T + biases ----
    mma_gemm<64, 32, 32, 0><<<dim3(1, 32), 256, SM64>>>(
        W_ih, 1536, 1536, xcat, 1536,
        W_hh, HDIM, HDIM, h0, HDIM,
        4 * HDIM, gatesT, BATCH, b_ih, b_hh, nullptr, nullptr, nullptr);
    lstm_cell<<<BATCH * HDIM / 256, 256>>>(gatesT, c0, out + OFF_H1, out + OFF_C1, xout);

    // ---- Output projection (as out^T: M=V rows, N=64) + log_softmax ----
    mma_gemm<64, 32, 32, 1><<<dim3(1, (VDIM + 127) / 128), 256, SM64>>>(
        W_out, 2 * HDIM, 2 * HDIM, xout, 2 * HDIM,
        nullptr, 0, 0, nullptr, 0,
        VDIM, out, VDIM, b_out, nullptr, nullptr, nullptr, nullptr);
    logsoftmax_rows<<<BATCH, 1024>>>(out);
}

// round 15
// speedup vs baseline: 4.5150x; 1.2035x over previous
#include <cuda_runtime.h>
#include <cstdint>
#include <math.h>

// ---------------------------------------------------------------------------
// Problem constants
// ---------------------------------------------------------------------------
#define BATCH 64
#define HDIM  1024
#define EDIM  512
#define VDIM  50000
#define LQ    32
#define LD    400

// Output layout (tuple concat, float32)
#define OFF_OUT   0
#define OFF_H1    (3200000)
#define OFF_C1    (OFF_H1 + 65536)
#define OFF_DH    (OFF_C1 + 65536)
#define OFF_DC    (OFF_DH + 65536)
#define OFF_DOCW  (OFF_DC + 65536)

#define PARTW 32   // score partials per row: 8 n-blocks x 4 n-warps

// ---------------------------------------------------------------------------
// Scratch (device globals: no allocations allowed)
// ---------------------------------------------------------------------------
__device__ float g_qpart [HDIM * BATCH];            // qpartT[e,b]
__device__ float g_partq [LQ * BATCH * PARTW];
__device__ float g_wq    [BATCH * LQ];
__device__ float g_docq  [BATCH * 2 * HDIM];        // [h_last | q_ctx]
__device__ float g_dqpart[HDIM * BATCH];            // dqpartT[e,b]
__device__ float g_partd [LD * BATCH * PARTW];
__device__ float g_wd    [BATCH * LD];
__device__ float g_xcat  [BATCH * 1536];            // [embedded(512) | doc_ctx(1024)]
__device__ float g_xout  [BATCH * 2048];            // [h1 | doc_ctx]
__device__ float g_gates [4096 * BATCH];            // gatesT[g,b]
__device__ float g_dgates[4096 * BATCH];            // dgatesT[g,b]
__device__ float g_skbuf [8 * 4096 * BATCH];        // split-K partials [z][m][b]

// ---------------------------------------------------------------------------
// PTX helpers (portable: cp.async + mma.sync)
// ---------------------------------------------------------------------------
__device__ __forceinline__ uint32_t smem_u32_of(const void* p) {
    uint32_t a;
    asm("{ .reg .u64 t; cvta.to.shared.u64 t, %1; cvt.u32.u64 %0, t; }" : "=r"(a) : "l"(p));
    return a;
}

__device__ __forceinline__ void cp_async16(uint32_t dst, const void* src, uint32_t sz) {
    asm volatile("cp.async.cg.shared.global [%0], [%1], 16, %2;"
                 :: "r"(dst), "l"(src), "r"(sz) : "memory");
}

// D(16x8) += A(16x8 tf32, row) * B(8x8 tf32, col)
// Raw fp32 bits: HW ignores the low 13 mantissa bits of tf32 operands.
__device__ __forceinline__ void mma_tf32(float* c, const uint32_t* a, const uint32_t* b) {
    asm volatile(
        "mma.sync.aligned.m16n8k8.row.col.f32.tf32.tf32.f32 "
        "{%0,%1,%2,%3}, {%4,%5,%6,%7}, {%8,%9}, {%0,%1,%2,%3};"
        : "+f"(c[0]), "+f"(c[1]), "+f"(c[2]), "+f"(c[3])
        : "r"(a[0]), "r"(a[1]), "r"(a[2]), "r"(a[3]), "r"(b[0]), "r"(b[1]));
}

// ---------------------------------------------------------------------------
// tf32 mma.sync GEMM:  C[M, N] = sum_pairs A_p[M, K_p] * B_p[N, K_p]^T
// BM=128, BK=32, 256 threads = 8 warps arranged (128/WM) x (BN/WN).
// Double-buffered cp.async, 2 CTAs/SM (launch_bounds), smem stride 36 floats.
// grid.z splits the K-chunk range (deterministic split-K; z=1 => full K).
// EPI 0: dst[m*ldc + n] = acc + bias1[m] + bias2[m]
// EPI 1: dst[n*ldc + m] = acc + bias1[m]            (transposed store)
// EPI 2: part[m*PARTW + bx*NW + wn] = sum_n tanh(acc + qadd[n*64+(m&63)] + bias1[n])*v[n]
// EPI 3: dst[(z*M + m)*64 + n] = acc                 (raw split-K partial, BN=64)
// ---------------------------------------------------------------------------
template<int BN, int WM, int WN, int EPI>
__global__ __launch_bounds__(256, 2)
void mma_gemm(const float* __restrict__ A1, int lda1, int K1,
              const float* __restrict__ B1, int ldb1,
              const float* __restrict__ A2, int lda2, int K2,
              const float* __restrict__ B2, int ldb2,
              int M,
              float* __restrict__ dst, int ldc,
              const float* __restrict__ bias1, const float* __restrict__ bias2,
              const float* __restrict__ qadd, const float* __restrict__ vvec,
              float* __restrict__ part)
{
    constexpr int MW  = 128 / WM;                 // warps along M
    constexpr int NW  = BN / WN;                  // warps along N
    static_assert(MW * NW == 8, "8 warps");
    constexpr int MT  = WM / 16;
    constexpr int NT  = WN / 8;
    constexpr int AST = 36;                       // smem row stride (floats)
    constexpr int SF  = 128 * AST + BN * AST;     // floats per stage

    extern __shared__ float smem[];
    const uint32_t smem_addr = smem_u32_of(smem);

    const int tid  = threadIdx.x;
    const int w    = tid >> 5;
    const int lane = tid & 31;
    const int g    = lane >> 2;
    const int t    = lane & 3;
    const int wmid = w % MW;
    const int wnid = w / MW;
    const int wm0  = wmid * WM;
    const int wn0  = wnid * WN;
    const int m0   = blockIdx.y * 128;
    const int n0   = blockIdx.x * BN;

    const int nk1 = K1 >> 5;
    const int nk  = nk1 + (K2 >> 5);
    const int ck  = (nk + (int)gridDim.z - 1) / (int)gridDim.z;
    const int c0  = blockIdx.z * ck;
    const int c1  = min(nk, c0 + ck);

    float acc[MT][NT][4];
#pragma unroll
    for (int mt = 0; mt < MT; mt++)
#pragma unroll
        for (int nt = 0; nt < NT; nt++)
#pragma unroll
            for (int j = 0; j < 4; j++) acc[mt][nt][j] = 0.f;

    auto load_chunk = [&](int stage, int c) {
        const float* Ap; const float* Bp; int lda, ldb, koff;
        if (c < nk1) { Ap = A1; Bp = B1; lda = lda1; ldb = ldb1; koff = c * 32; }
        else         { Ap = A2; Bp = B2; lda = lda2; ldb = ldb2; koff = (c - nk1) * 32; }
        const uint32_t sa = smem_addr + stage * SF * 4;
        const uint32_t sb = sa + 128 * AST * 4;
#pragma unroll
        for (int i = 0; i < 4; i++) {             // A: 128 rows x 32 floats
            int seg = i * 256 + tid;
            int row = seg >> 3, c4 = (seg & 7) * 4;
            int gr  = m0 + row;
            int grc = gr < M ? gr : (M - 1);
            cp_async16(sa + (uint32_t)(row * AST + c4) * 4,
                       Ap + (size_t)grc * lda + koff + c4,
                       gr < M ? 16u : 0u);
        }
#pragma unroll
        for (int i = 0; i < BN / 32; i++) {       // B: BN rows x 32 floats
            int seg = i * 256 + tid;
            int row = seg >> 3, c4 = (seg & 7) * 4;
            cp_async16(sb + (uint32_t)(row * AST + c4) * 4,
                       Bp + (size_t)(n0 + row) * ldb + koff + c4, 16u);
        }
        asm volatile("cp.async.commit_group;" ::: "memory");
    };

    load_chunk(0, c0);

#pragma unroll 1
    for (int c = c0; c < c1; c++) {
        const int s = (c - c0) & 1;
        if (c + 1 < c1) {
            load_chunk(s ^ 1, c + 1);
            asm volatile("cp.async.wait_group 1;" ::: "memory");
        } else {
            asm volatile("cp.async.wait_group 0;" ::: "memory");
        }
        __syncthreads();

        const float* sA = smem + s * SF;
        const float* sB = sA + 128 * AST;

#pragma unroll
        for (int kk = 0; kk < 4; kk++) {
            const int kb = kk * 8;
            uint32_t ar[MT][4];
#pragma unroll
            for (int mt = 0; mt < MT; mt++) {
                const int r = wm0 + mt * 16 + g;
                ar[mt][0] = __float_as_uint(sA[(r)     * AST + kb + t]);
                ar[mt][1] = __float_as_uint(sA[(r + 8) * AST + kb + t]);
                ar[mt][2] = __float_as_uint(sA[(r)     * AST + kb + t + 4]);
                ar[mt][3] = __float_as_uint(sA[(r + 8) * AST + kb + t + 4]);
            }
#pragma unroll
            for (int nt = 0; nt < NT; nt++) {
                uint32_t br[2];
                const int r = wn0 + nt * 8 + g;
                br[0] = __float_as_uint(sB[r * AST + kb + t]);
                br[1] = __float_as_uint(sB[r * AST + kb + t + 4]);
#pragma unroll
                for (int mt = 0; mt < MT; mt++)
                    mma_tf32(acc[mt][nt], ar[mt], br);
            }
        }
        __syncthreads();
    }

    // ---- Epilogue ----
    if constexpr (EPI == 2) {
#pragma unroll
        for (int mt = 0; mt < MT; mt++)
#pragma unroll
            for (int rh = 0; rh < 2; rh++) {
                const int m = m0 + wm0 + mt * 16 + g + rh * 8;
                const int b = m & (BATCH - 1);
                float p = 0.f;
#pragma unroll
                for (int nt = 0; nt < NT; nt++)
#pragma unroll
                    for (int cj = 0; cj < 2; cj++) {
                        const int n = n0 + wn0 + nt * 8 + 2 * t + cj;
                        float e = tanhf(acc[mt][nt][rh * 2 + cj]
                                        + qadd[n * BATCH + b] + bias1[n]);
                        p = fmaf(e, vvec[n], p);
                    }
                p += __shfl_xor_sync(0xffffffffu, p, 1);
                p += __shfl_xor_sync(0xffffffffu, p, 2);
                if (t == 0 && m < M)
                    part[(size_t)m * PARTW + blockIdx.x * NW + wnid] = p;
            }
    } else if constexpr (EPI == 3) {
#pragma unroll
        for (int mt = 0; mt < MT; mt++)
#pragma unroll
            for (int rh = 0; rh < 2; rh++) {
                const int m = m0 + wm0 + mt * 16 + g + rh * 8;
                if (m >= M) continue;
#pragma unroll
                for (int nt = 0; nt < NT; nt++) {
                    const int n = wn0 + nt * 8 + 2 * t;
                    float* d = dst + ((size_t)blockIdx.z * M + m) * 64 + n;
                    d[0] = acc[mt][nt][rh * 2 + 0];
                    d[1] = acc[mt][nt][rh * 2 + 1];
                }
            }
    } else {
#pragma unroll
        for (int mt = 0; mt < MT; mt++)
#pragma unroll
            for (int rh = 0; rh < 2; rh++) {
                const int m = m0 + wm0 + mt * 16 + g + rh * 8;
                if (m >= M) continue;
                float bb = 0.f;
                if (bias1) bb += bias1[m];
                if (EPI == 0 && bias2) bb += bias2[m];
#pragma unroll
                for (int nt = 0; nt < NT; nt++) {
                    const int n = n0 + wn0 + nt * 8 + 2 * t;
                    const float v0 = acc[mt][nt][rh * 2 + 0] + bb;
                    const float v1 = acc[mt][nt][rh * 2 + 1] + bb;
                    if constexpr (EPI == 0) {
                        dst[(size_t)m * ldc + n]     = v0;
                        dst[(size_t)m * ldc + n + 1] = v1;
                    } else {
                        dst[(size_t)(n)     * ldc + m] = v0;
                        dst[(size_t)(n + 1) * ldc + m] = v1;
                    }
                }
            }
    }
}

// split-K reduce: dst[m*64+n] = sum_z sk[(z*M + m)*64 + n] (+ bias1[m] + bias2[m])
__global__ void sk_reduce(const float* __restrict__ sk, int S, int M,
                          float* __restrict__ dst,
                          const float* __restrict__ b1, const float* __restrict__ b2)
{
    int idx = blockIdx.x * blockDim.x + threadIdx.x;  // over M*64
    int m = idx >> 6;
    float s = 0.f;
    for (int z = 0; z < S; z++) s += sk[(size_t)z * M * 64 + idx];
    if (b1) s += b1[m];
    if (b2) s += b2[m];
    dst[idx] = s;
}

// ---------------------------------------------------------------------------
// Small helper kernels
// ---------------------------------------------------------------------------
__global__ void gather_embed(const int* __restrict__ idx,
                             const float* __restrict__ embed,
                             float* __restrict__ xcat)
{
    int b = blockIdx.x, e = threadIdx.x;              // 512 threads
    xcat[b * 1536 + e] = embed[(size_t)idx[b] * EDIM + e];
}

__global__ void copy_hlast(const float* __restrict__ h0, float* __restrict__ docq)
{
    int b = blockIdx.x, h = threadIdx.x;              // 1024 threads
    docq[b * 2048 + h] = h0[b * HDIM + h];
}

__device__ __forceinline__ float sum_part(const float* __restrict__ p) {
    float s = 0.f;
#pragma unroll
    for (int i = 0; i < PARTW; i++) s += p[i];
    return s;
}

__global__ void qsoftmax(const float* __restrict__ part, float* __restrict__ w)
{
    int b = blockIdx.x, t = threadIdx.x;              // 32 threads
    float s = sum_part(part + ((size_t)t * BATCH + b) * PARTW);
    float mx = s;
#pragma unroll
    for (int o = 16; o; o >>= 1) mx = fmaxf(mx, __shfl_xor_sync(0xffffffffu, mx, o));
    float e = expf(s - mx);
    float sum = e;
#pragma unroll
    for (int o = 16; o; o >>= 1) sum += __shfl_xor_sync(0xffffffffu, sum, o);
    w[b * LQ + t] = e / sum;
}

__global__ void dsoftmax(const float* __restrict__ part,
                         float* __restrict__ w, float* __restrict__ outw)
{
    __shared__ float sh[256];
    int b = blockIdx.x, tid = threadIdx.x;            // 256 threads
    float mx = -1e30f;
    for (int t = tid; t < LD; t += 256)
        mx = fmaxf(mx, sum_part(part + ((size_t)t * BATCH + b) * PARTW));
    sh[tid] = mx; __syncthreads();
    for (int s = 128; s > 0; s >>= 1) { if (tid < s) sh[tid] = fmaxf(sh[tid], sh[tid + s]); __syncthreads(); }
    mx = sh[0]; __syncthreads();

    float sum = 0.f;
    for (int t = tid; t < LD; t += 256)
        sum += expf(sum_part(part + ((size_t)t * BATCH + b) * PARTW) - mx);
    sh[tid] = sum; __syncthreads();
    for (int s = 128; s > 0; s >>= 1) { if (tid < s) sh[tid] += sh[tid + s]; __syncthreads(); }
    float tot = sh[0];

    for (int t = tid; t < LD; t += 256) {
        float s = sum_part(part + ((size_t)t * BATCH + b) * PARTW);
        float v = expf(s - mx) / tot;
        w[b * LD + t]    = v;
        outw[b * LD + t] = v;
    }
}

__global__ void weighted_ctx(const float* __restrict__ w, int T,
                             const float* __restrict__ enc,
                             float* __restrict__ dst1, int ld1, int off1,
                             float* __restrict__ dst2, int ld2, int off2)
{
    int b = blockIdx.y;
    int h = blockIdx.x * blockDim.x + threadIdx.x;
    const float* wb = w + b * T;
    float a = 0.f;
#pragma unroll 4
    for (int t = 0; t < T; t++)
        a = fmaf(wb[t], enc[((size_t)t * BATCH + b) * HDIM + h], a);
    dst1[(size_t)b * ld1 + off1 + h] = a;
    if (dst2) dst2[(size_t)b * ld2 + off2 + h] = a;
}

__device__ __forceinline__ float sigf(float x) { return 1.f / (1.f + expf(-x)); }

// gates stored transposed: gT[g * 64 + b]
__global__ void lstm_cell(const float* __restrict__ gT,
                          const float* __restrict__ cprev,
                          float* __restrict__ hout, float* __restrict__ cout,
                          float* __restrict__ hout2)
{
    int idx = blockIdx.x * blockDim.x + threadIdx.x;  // B*H, b fastest
    int b = idx & 63, h = idx >> 6;
    float i  = sigf (gT[(h)        * BATCH + b]);
    float f  = sigf (gT[(1024 + h) * BATCH + b]);
    float gg = tanhf(gT[(2048 + h) * BATCH + b]);
    float o  = sigf (gT[(3072 + h) * BATCH + b]);
    float c  = f * cprev[b * HDIM + h] + i * gg;
    float hh = o * tanhf(c);
    hout[b * HDIM + h] = hh;
    cout[b * HDIM + h] = c;
    if (hout2) hout2[b * 2048 + h] = hh;
}

// online log-softmax: one read pass for (max, sum), one write pass
__global__ void logsoftmax_rows(float* __restrict__ x)
{
    __shared__ float shm[1024], shs[1024];
    int b = blockIdx.x, tid = threadIdx.x;            // 1024 threads
    float* row = x + (size_t)b * VDIM;

    float mx = -1e30f, sum = 0.f;
    for (int i = tid; i < VDIM; i += 1024) {
        float v = row[i];
        float nm = fmaxf(mx, v);
        sum = sum * expf(mx - nm) + expf(v - nm);
        mx = nm;
    }
    shm[tid] = mx; shs[tid] = sum; __syncthreads();
    for (int s = 512; s > 0; s >>= 1) {
        if (tid < s) {
            float m2 = shm[tid + s], s2 = shs[tid + s];
            float nm = fmaxf(shm[tid], m2);
            shs[tid] = shs[tid] * expf(shm[tid] - nm) + s2 * expf(m2 - nm);
            shm[tid] = nm;
        }
        __syncthreads();
    }
    float lse = shm[0] + logf(shs[0]);

    for (int i = tid; i < VDIM; i += 1024) row[i] -= lse;
}

// ---------------------------------------------------------------------------
// Launcher
// ---------------------------------------------------------------------------
extern "C" void kernel_launch(void* const* d_in, const int* in_sizes, int n_in,
                              void* d_out, int out_size)
{
    (void)in_sizes; (void)n_in; (void)out_size;
    const int*   input = (const int*)  d_in[0];
    const float* h0    = (const float*)d_in[1];
    const float* c0    = (const float*)d_in[2];
    const float* dh0   = (const float*)d_in[3];
    const float* dc0   = (const float*)d_in[4];
    const float* qo    = (const float*)d_in[5];
    const float* enc   = (const float*)d_in[6];
    const float* embed = (const float*)d_in[7];
    const float* W_qa  = (const float*)d_in[8];
    const float* b_qa  = (const float*)d_in[9];
    const float* v_q   = (const float*)d_in[10];
    const float* W_da  = (const float*)d_in[11];
    const float* b_da  = (const float*)d_in[12];
    const float* v_d   = (const float*)d_in[13];
    const float* W_ih  = (const float*)d_in[14];
    const float* W_hh  = (const float*)d_in[15];
    const float* b_ih  = (const float*)d_in[16];
    const float* b_hh  = (const float*)d_in[17];
    const float* Wd_ih = (const float*)d_in[18];
    const float* Wd_hh = (const float*)d_in[19];
    const float* bd_ih = (const float*)d_in[20];
    const float* bd_hh = (const float*)d_in[21];
    const float* W_out = (const float*)d_in[22];
    const float* b_out = (const float*)d_in[23];
    float* out = (float*)d_out;

    float *qpartT, *partq, *wq, *docq, *dqpartT, *partd, *wd, *xcat, *xout,
          *gatesT, *dgatesT, *skbuf;
    cudaGetSymbolAddress((void**)&qpartT,  g_qpart);
    cudaGetSymbolAddress((void**)&partq,   g_partq);
    cudaGetSymbolAddress((void**)&wq,      g_wq);
    cudaGetSymbolAddress((void**)&docq,    g_docq);
    cudaGetSymbolAddress((void**)&dqpartT, g_dqpart);
    cudaGetSymbolAddress((void**)&partd,   g_partd);
    cudaGetSymbolAddress((void**)&wd,      g_wd);
    cudaGetSymbolAddress((void**)&xcat,    g_xcat);
    cudaGetSymbolAddress((void**)&xout,    g_xout);
    cudaGetSymbolAddress((void**)&gatesT,  g_gates);
    cudaGetSymbolAddress((void**)&dgatesT, g_dgates);
    cudaGetSymbolAddress((void**)&skbuf,   g_skbuf);

    // smem: 2 stages * (128 + BN) rows * 36 floats * 4 B
    const int SM128 = 2 * (128 + 128) * 36 * 4;   // 73728  -> 2 CTAs/SM
    const int SM64  = 2 * (128 +  64) * 36 * 4;   // 55296
    cudaFuncSetAttribute((const void*)mma_gemm<128, 64, 32, 2>,
                         cudaFuncAttributeMaxDynamicSharedMemorySize, SM128);
    cudaFuncSetAttribute((const void*)mma_gemm<64, 32, 32, 3>,
                         cudaFuncAttributeMaxDynamicSharedMemorySize, SM64);
    cudaFuncSetAttribute((const void*)mma_gemm<64, 32, 32, 1>,
                         cudaFuncAttributeMaxDynamicSharedMemorySize, SM64);

    gather_embed<<<BATCH, 512>>>(input, embed, xcat);
    copy_hlast  <<<BATCH, 1024>>>(h0, docq);

    // ---- Query attention ----
    // qpartT[e,b] = sum_k W_qa[e,k] * h0[b,k]   (split-K x8)
    mma_gemm<64, 32, 32, 3><<<dim3(1, 8, 8), 256, SM64>>>(
        W_qa, 2 * HDIM, HDIM, h0, HDIM,
        nullptr, 0, 0, nullptr, 0,
        HDIM, skbuf, 64, nullptr, nullptr, nullptr, nullptr, nullptr);
    sk_reduce<<<HDIM * 64 / 256, 256>>>(skbuf, 8, HDIM, qpartT, nullptr, nullptr);
    // fused energy + per-(row, nblk, nwarp) score partials over query_outputs
    mma_gemm<128, 64, 32, 2><<<dim3(8, 16), 256, SM128>>>(
        qo, HDIM, HDIM, W_qa + HDIM, 2 * HDIM,
        nullptr, 0, 0, nullptr, 0,
        LQ * BATCH, nullptr, 0, b_qa, nullptr, qpartT, v_q, partq);
    qsoftmax<<<BATCH, 32>>>(partq, wq);
    weighted_ctx<<<dim3(HDIM / 256, BATCH), 256>>>(wq, LQ, qo,
        docq, 2048, 1024, nullptr, 0, 0);

    // ---- Doc attention ----
    mma_gemm<64, 32, 32, 3><<<dim3(1, 8, 8), 256, SM64>>>(
        W_da, 3 * HDIM, 2 * HDIM, docq, 2 * HDIM,
        nullptr, 0, 0, nullptr, 0,
        HDIM, skbuf, 64, nullptr, nullptr, nullptr, nullptr, nullptr);
    sk_reduce<<<HDIM * 64 / 256, 256>>>(skbuf, 8, HDIM, dqpartT, nullptr, nullptr);
    mma_gemm<128, 64, 32, 2><<<dim3(8, 200), 256, SM128>>>(
        enc, HDIM, HDIM, W_da + 2 * HDIM, 3 * HDIM,
        nullptr, 0, 0, nullptr, 0,
        LD * BATCH, nullptr, 0, b_da, nullptr, dqpartT, v_d, partd);
    dsoftmax<<<BATCH, 256>>>(partd, wd, out + OFF_DOCW);
    weighted_ctx<<<dim3(HDIM / 256, BATCH), 256>>>(wd, LD, enc,
        xcat, 1536, 512, xout, 2048, 1024);

    // ---- Distraction LSTM: dgatesT = Wd_ih@doc_ctx^T + Wd_hh@dh0^T + biases ----
    mma_gemm<64, 32, 32, 3><<<dim3(1, 32, 8), 256, SM64>>>(
        Wd_ih, HDIM, HDIM, xcat + 512, 1536,
        Wd_hh, HDIM, HDIM, dh0, HDIM,
        4 * HDIM, skbuf, 64, nullptr, nullptr, nullptr, nullptr, nullptr);
    sk_reduce<<<4 * HDIM * 64 / 256, 256>>>(skbuf, 8, 4 * HDIM, dgatesT, bd_ih, bd_hh);
    lstm_cell<<<BATCH * HDIM / 256, 256>>>(dgatesT, dc0, out + OFF_DH, out + OFF_DC, nullptr);

    // ---- Main LSTM: gatesT = W_ih@[emb|doc_ctx]^T + W_hh@h0^T + biases ----
    mma_gemm<64, 32, 32, 3><<<dim3(1, 32, 8), 256, SM64>>>(
        W_ih, 1536, 1536, xcat, 1536,
        W_hh, HDIM, HDIM, h0, HDIM,
        4 * HDIM, skbuf, 64, nullptr, nullptr, nullptr, nullptr, nullptr);
    sk_reduce<<<4 * HDIM * 64 / 256, 256>>>(skbuf, 8, 4 * HDIM, gatesT, b_ih, b_hh);
    lstm_cell<<<BATCH * HDIM / 256, 256>>>(gatesT, c0, out + OFF_H1, out + OFF_C1, xout);

    // ---- Output projection (as out^T: M=V rows, N=64) + log_softmax ----
    mma_gemm<64, 32, 32, 1><<<dim3(1, (VDIM + 127) / 128), 256, SM64>>>(
        W_out, 2 * HDIM, 2 * HDIM, xout, 2 * HDIM,
        nullptr, 0, 0, nullptr, 0,
        VDIM, out, VDIM, b_out, nullptr, nullptr, nullptr, nullptr);
    logsoftmax_rows<<<BATCH, 1024>>>(out);
}

// round 16
// speedup vs baseline: 4.6832x; 1.0373x over previous
#include <cuda_runtime.h>
#include <cstdint>
#include <math.h>

// ---------------------------------------------------------------------------
// Problem constants
// ---------------------------------------------------------------------------
#define BATCH 64
#define HDIM  1024
#define EDIM  512
#define VDIM  50000
#define LQ    32
#define LD    400

// Output layout (tuple concat, float32)
#define OFF_OUT   0
#define OFF_H1    (3200000)
#define OFF_C1    (OFF_H1 + 65536)
#define OFF_DH    (OFF_C1 + 65536)
#define OFF_DC    (OFF_DH + 65536)
#define OFF_DOCW  (OFF_DC + 65536)

#define PARTW 32   // score partials per row: 8 n-blocks x 4 n-warps

// ---------------------------------------------------------------------------
// Scratch (device globals: no allocations allowed)
// ---------------------------------------------------------------------------
__device__ float g_qpart [HDIM * BATCH];            // qpartT[e,b]
__device__ float g_partq [LQ * BATCH * PARTW];
__device__ float g_docq  [BATCH * 2 * HDIM];        // [h_last | q_ctx]
__device__ float g_dqpart[HDIM * BATCH];            // dqpartT[e,b]
__device__ float g_partd [LD * BATCH * PARTW];
__device__ float g_xcat  [BATCH * 1536];            // [embedded(512) | doc_ctx(1024)]
__device__ float g_xout  [BATCH * 2048];            // [h1 | doc_ctx]
__device__ float g_skbuf [8 * 4096 * BATCH];        // split-K partials [z][m][b]

// ---------------------------------------------------------------------------
// Math helpers (fast, MUFU-based)
// ---------------------------------------------------------------------------
__device__ __forceinline__ float fast_exp(float x) { return __expf(x); }
__device__ __forceinline__ float fast_tanh(float x) {
    float e = __expf(-2.f * fabsf(x));
    float t = __fdividef(1.f - e, 1.f + e);
    return copysignf(t, x);
}
__device__ __forceinline__ float sigf(float x) { return __fdividef(1.f, 1.f + __expf(-x)); }

// ---------------------------------------------------------------------------
// PTX helpers (portable: cp.async + mma.sync)
// ---------------------------------------------------------------------------
__device__ __forceinline__ uint32_t smem_u32_of(const void* p) {
    uint32_t a;
    asm("{ .reg .u64 t; cvta.to.shared.u64 t, %1; cvt.u32.u64 %0, t; }" : "=r"(a) : "l"(p));
    return a;
}

__device__ __forceinline__ void cp_async16(uint32_t dst, const void* src, uint32_t sz) {
    asm volatile("cp.async.cg.shared.global [%0], [%1], 16, %2;"
                 :: "r"(dst), "l"(src), "r"(sz) : "memory");
}

// D(16x8) += A(16x8 tf32, row) * B(8x8 tf32, col)
// Raw fp32 bits: HW ignores the low 13 mantissa bits of tf32 operands.
__device__ __forceinline__ void mma_tf32(float* c, const uint32_t* a, const uint32_t* b) {
    asm volatile(
        "mma.sync.aligned.m16n8k8.row.col.f32.tf32.tf32.f32 "
        "{%0,%1,%2,%3}, {%4,%5,%6,%7}, {%8,%9}, {%0,%1,%2,%3};"
        : "+f"(c[0]), "+f"(c[1]), "+f"(c[2]), "+f"(c[3])
        : "r"(a[0]), "r"(a[1]), "r"(a[2]), "r"(a[3]), "r"(b[0]), "r"(b[1]));
}

// ---------------------------------------------------------------------------
// tf32 mma.sync GEMM:  C[M, N] = sum_pairs A_p[M, K_p] * B_p[N, K_p]^T
// BM=128, BK=32, 256 threads = 8 warps arranged (128/WM) x (BN/WN).
// 3-stage cp.async pipeline, 2 CTAs/SM, smem stride 36 floats.
// grid.z splits the K-chunk range (deterministic split-K; z=1 => full K).
// EPI 0: dst[m*ldc + n] = acc + bias1[m] + bias2[m]
// EPI 1: dst[n*ldc + m] = acc + bias1[m]            (transposed store)
// EPI 2: part[m*PARTW + bx*NW + wn] = sum_n tanh(acc + qadd[n*64+(m&63)] + bias1[n])*v[n]
// EPI 3: dst[(z*M + m)*64 + n] = acc                 (raw split-K partial, BN=64)
// ---------------------------------------------------------------------------
template<int BN, int WM, int WN, int EPI>
__global__ __launch_bounds__(256, 2)
void mma_gemm(const float* __restrict__ A1, int lda1, int K1,
              const float* __restrict__ B1, int ldb1,
              const float* __restrict__ A2, int lda2, int K2,
              const float* __restrict__ B2, int ldb2,
              int M,
              float* __restrict__ dst, int ldc,
              const float* __restrict__ bias1, const float* __restrict__ bias2,
              const float* __restrict__ qadd, const float* __restrict__ vvec,
              float* __restrict__ part)
{
    constexpr int MW  = 128 / WM;                 // warps along M
    constexpr int NW  = BN / WN;                  // warps along N
    static_assert(MW * NW == 8, "8 warps");
    constexpr int MT  = WM / 16;
    constexpr int NT  = WN / 8;
    constexpr int AST = 36;                       // smem row stride (floats)
    constexpr int SF  = 128 * AST + BN * AST;     // floats per stage

    extern __shared__ float smem[];
    const uint32_t smem_addr = smem_u32_of(smem);

    const int tid  = threadIdx.x;
    const int w    = tid >> 5;
    const int lane = tid & 31;
    const int g    = lane >> 2;
    const int t    = lane & 3;
    const int wmid = w % MW;
    const int wnid = w / MW;
    const int wm0  = wmid * WM;
    const int wn0  = wnid * WN;
    const int m0   = blockIdx.y * 128;
    const int n0   = blockIdx.x * BN;

    const int nk1 = K1 >> 5;
    const int nk  = nk1 + (K2 >> 5);
    const int ck  = (nk + (int)gridDim.z - 1) / (int)gridDim.z;
    const int c0  = blockIdx.z * ck;
    const int c1  = min(nk, c0 + ck);

    float acc[MT][NT][4];
#pragma unroll
    for (int mt = 0; mt < MT; mt++)
#pragma unroll
        for (int nt = 0; nt < NT; nt++)
#pragma unroll
            for (int j = 0; j < 4; j++) acc[mt][nt][j] = 0.f;

    auto load_chunk = [&](int stage, int c) {
        const float* Ap; const float* Bp; int lda, ldb, koff;
        if (c < nk1) { Ap = A1; Bp = B1; lda = lda1; ldb = ldb1; koff = c * 32; }
        else         { Ap = A2; Bp = B2; lda = lda2; ldb = ldb2; koff = (c - nk1) * 32; }
        const uint32_t sa = smem_addr + stage * SF * 4;
        const uint32_t sb = sa + 128 * AST * 4;
#pragma unroll
        for (int i = 0; i < 4; i++) {             // A: 128 rows x 32 floats
            int seg = i * 256 + tid;
            int row = seg >> 3, c4 = (seg & 7) * 4;
            int gr  = m0 + row;
            int grc = gr < M ? gr : (M - 1);
            cp_async16(sa + (uint32_t)(row * AST + c4) * 4,
                       Ap + (size_t)grc * lda + koff + c4,
                       gr < M ? 16u : 0u);
        }
#pragma unroll
        for (int i = 0; i < BN / 32; i++) {       // B: BN rows x 32 floats
            int seg = i * 256 + tid;
            int row = seg >> 3, c4 = (seg & 7) * 4;
            cp_async16(sb + (uint32_t)(row * AST + c4) * 4,
                       Bp + (size_t)(n0 + row) * ldb + koff + c4, 16u);
        }
        asm volatile("cp.async.commit_group;" ::: "memory");
    };

    load_chunk(0, c0);
    if (c0 + 1 < c1) load_chunk(1, c0 + 1);

#pragma unroll 1
    for (int c = c0; c < c1; c++) {
        const int s = (c - c0) % 3;
        if (c + 2 < c1) load_chunk((s + 2) % 3, c + 2);
        const int rem = c1 - 1 - c;
        if (rem >= 2)      asm volatile("cp.async.wait_group 2;" ::: "memory");
        else if (rem == 1) asm volatile("cp.async.wait_group 1;" ::: "memory");
        else               asm volatile("cp.async.wait_group 0;" ::: "memory");
        __syncthreads();

        const float* sA = smem + s * SF;
        const float* sB = sA + 128 * AST;

#pragma unroll
        for (int kk = 0; kk < 4; kk++) {
            const int kb = kk * 8;
            uint32_t ar[MT][4];
#pragma unroll
            for (int mt = 0; mt < MT; mt++) {
                const int r = wm0 + mt * 16 + g;
                ar[mt][0] = __float_as_uint(sA[(r)     * AST + kb + t]);
                ar[mt][1] = __float_as_uint(sA[(r + 8) * AST + kb + t]);
                ar[mt][2] = __float_as_uint(sA[(r)     * AST + kb + t + 4]);
                ar[mt][3] = __float_as_uint(sA[(r + 8) * AST + kb + t + 4]);
            }
#pragma unroll
            for (int nt = 0; nt < NT; nt++) {
                uint32_t br[2];
                const int r = wn0 + nt * 8 + g;
                br[0] = __float_as_uint(sB[r * AST + kb + t]);
                br[1] = __float_as_uint(sB[r * AST + kb + t + 4]);
#pragma unroll
                for (int mt = 0; mt < MT; mt++)
                    mma_tf32(acc[mt][nt], ar[mt], br);
            }
        }
        __syncthreads();
    }

    // ---- Epilogue ----
    if constexpr (EPI == 2) {
#pragma unroll
        for (int mt = 0; mt < MT; mt++)
#pragma unroll
            for (int rh = 0; rh < 2; rh++) {
                const int m = m0 + wm0 + mt * 16 + g + rh * 8;
                const int b = m & (BATCH - 1);
                float p = 0.f;
#pragma unroll
                for (int nt = 0; nt < NT; nt++)
#pragma unroll
                    for (int cj = 0; cj < 2; cj++) {
                        const int n = n0 + wn0 + nt * 8 + 2 * t + cj;
                        float e = fast_tanh(acc[mt][nt][rh * 2 + cj]
                                            + qadd[n * BATCH + b] + bias1[n]);
                        p = fmaf(e, vvec[n], p);
                    }
                p += __shfl_xor_sync(0xffffffffu, p, 1);
                p += __shfl_xor_sync(0xffffffffu, p, 2);
                if (t == 0 && m < M)
                    part[(size_t)m * PARTW + blockIdx.x * NW + wnid] = p;
            }
    } else if constexpr (EPI == 3) {
#pragma unroll
        for (int mt = 0; mt < MT; mt++)
#pragma unroll
            for (int rh = 0; rh < 2; rh++) {
                const int m = m0 + wm0 + mt * 16 + g + rh * 8;
                if (m >= M) continue;
#pragma unroll
                for (int nt = 0; nt < NT; nt++) {
                    const int n = wn0 + nt * 8 + 2 * t;
                    float* d = dst + ((size_t)blockIdx.z * M + m) * 64 + n;
                    d[0] = acc[mt][nt][rh * 2 + 0];
                    d[1] = acc[mt][nt][rh * 2 + 1];
                }
            }
    } else {
#pragma unroll
        for (int mt = 0; mt < MT; mt++)
#pragma unroll
            for (int rh = 0; rh < 2; rh++) {
                const int m = m0 + wm0 + mt * 16 + g + rh * 8;
                if (m >= M) continue;
                float bb = 0.f;
                if (bias1) bb += bias1[m];
                if (EPI == 0 && bias2) bb += bias2[m];
#pragma unroll
                for (int nt = 0; nt < NT; nt++) {
                    const int n = n0 + wn0 + nt * 8 + 2 * t;
                    const float v0 = acc[mt][nt][rh * 2 + 0] + bb;
                    const float v1 = acc[mt][nt][rh * 2 + 1] + bb;
                    if constexpr (EPI == 0) {
                        dst[(size_t)m * ldc + n]     = v0;
                        dst[(size_t)m * ldc + n + 1] = v1;
                    } else {
                        dst[(size_t)(n)     * ldc + m] = v0;
                        dst[(size_t)(n + 1) * ldc + m] = v1;
                    }
                }
            }
    }
}

// split-K reduce (no bias): dst[m*64+n] = sum_z sk[(z*M + m)*64 + n]
__global__ void sk_reduce(const float* __restrict__ sk, int M,
                          float* __restrict__ dst)
{
    int idx = blockIdx.x * blockDim.x + threadIdx.x;  // over M*64
    float s = 0.f;
#pragma unroll
    for (int z = 0; z < 8; z++) s += sk[(size_t)z * M * 64 + idx];
    dst[idx] = s;
}

// ---------------------------------------------------------------------------
// Fused helper kernels
// ---------------------------------------------------------------------------
// embedding gather + h_last copy
__global__ void init_misc(const int* __restrict__ idx,
                          const float* __restrict__ embed,
                          const float* __restrict__ h0,
                          float* __restrict__ xcat, float* __restrict__ docq)
{
    int b = blockIdx.x, t = threadIdx.x;              // 1024 threads
    docq[b * 2048 + t] = h0[b * HDIM + t];
    if (t < EDIM) xcat[b * 1536 + t] = embed[(size_t)idx[b] * EDIM + t];
}

__device__ __forceinline__ float sum_part(const float* __restrict__ p) {
    float s = 0.f;
#pragma unroll
    for (int i = 0; i < PARTW; i++) s += p[i];
    return s;
}

// fused query softmax + context: docq[b, 1024+h] = sum_t softmax(s)_t * qo[t,b,h]
__global__ void qctx(const float* __restrict__ part,
                     const float* __restrict__ qo,
                     float* __restrict__ docq)
{
    __shared__ float w[LQ];
    int b = blockIdx.y, tid = threadIdx.x;            // grid (4, 64) x 256
    if (tid < 32) {
        float s = sum_part(part + ((size_t)tid * BATCH + b) * PARTW);
        float mx = s;
#pragma unroll
        for (int o = 16; o; o >>= 1) mx = fmaxf(mx, __shfl_xor_sync(0xffffffffu, mx, o));
        float e = fast_exp(s - mx);
        float sum = e;
#pragma unroll
        for (int o = 16; o; o >>= 1) sum += __shfl_xor_sync(0xffffffffu, sum, o);
        w[tid] = __fdividef(e, sum);
    }
    __syncthreads();
    int h = blockIdx.x * 256 + tid;
    float a = 0.f;
#pragma unroll 4
    for (int t = 0; t < LQ; t++)
        a = fmaf(w[t], qo[((size_t)t * BATCH + b) * HDIM + h], a);
    docq[b * 2048 + 1024 + h] = a;
}

// fused doc softmax + context + doc_w output
__global__ void dctx(const float* __restrict__ part,
                     const float* __restrict__ enc,
                     float* __restrict__ outw,
                     float* __restrict__ xcat, float* __restrict__ xout)
{
    __shared__ float w[LD];
    __shared__ float red[256];
    int b = blockIdx.y, tid = threadIdx.x;            // grid (4, 64) x 256

    float mx = -1e30f;
    for (int t = tid; t < LD; t += 256) {
        float s = sum_part(part + ((size_t)t * BATCH + b) * PARTW);
        w[t] = s;
        mx = fmaxf(mx, s);
    }
    red[tid] = mx; __syncthreads();
    for (int s = 128; s > 0; s >>= 1) { if (tid < s) red[tid] = fmaxf(red[tid], red[tid + s]); __syncthreads(); }
    mx = red[0]; __syncthreads();

    float sum = 0.f;
    for (int t = tid; t < LD; t += 256) sum += fast_exp(w[t] - mx);
    red[tid] = sum; __syncthreads();
    for (int s = 128; s > 0; s >>= 1) { if (tid < s) red[tid] += red[tid + s]; __syncthreads(); }
    float inv = __fdividef(1.f, red[0]);
    __syncthreads();

    for (int t = tid; t < LD; t += 256) {
        float v = fast_exp(w[t] - mx) * inv;
        w[t] = v;
        if (blockIdx.x == 0) outw[b * LD + t] = v;
    }
    __syncthreads();

    int h = blockIdx.x * 256 + tid;
    float a = 0.f;
#pragma unroll 4
    for (int t = 0; t < LD; t++)
        a = fmaf(w[t], enc[((size_t)t * BATCH + b) * HDIM + h], a);
    xcat[b * 1536 + 512 + h]  = a;
    xout[b * 2048 + 1024 + h] = a;
}

// fused split-K reduce + biases + LSTM cell (gate partials in sk, [z][m][b])
__global__ void lstm_from_parts(const float* __restrict__ sk,
                                const float* __restrict__ b1, const float* __restrict__ b2,
                                const float* __restrict__ cprev,
                                float* __restrict__ hout, float* __restrict__ cout,
                                float* __restrict__ hout2)
{
    int idx = blockIdx.x * blockDim.x + threadIdx.x;  // B*H, b fastest
    int b = idx & 63, h = idx >> 6;
    float g4[4];
#pragma unroll
    for (int q = 0; q < 4; q++) {
        int m = q * 1024 + h;
        float s = b1[m] + b2[m];
#pragma unroll
        for (int z = 0; z < 8; z++) s += sk[((size_t)z * 4096 + m) * 64 + b];
        g4[q] = s;
    }
    float i  = sigf(g4[0]);
    float f  = sigf(g4[1]);
    float gg = fast_tanh(g4[2]);
    float o  = sigf(g4[3]);
    float c  = f * cprev[b * HDIM + h] + i * gg;
    float hh = o * fast_tanh(c);
    hout[b * HDIM + h] = hh;
    cout[b * HDIM + h] = c;
    if (hout2) hout2[b * 2048 + h] = hh;
}

// online log-softmax: one read pass for (max, sum), one write pass
__global__ void logsoftmax_rows(float* __restrict__ x)
{
    __shared__ float shm[1024], shs[1024];
    int b = blockIdx.x, tid = threadIdx.x;            // 1024 threads
    float* row = x + (size_t)b * VDIM;

    float mx = -1e30f, sum = 0.f;
    for (int i = tid; i < VDIM; i += 1024) {
        float v = row[i];
        float nm = fmaxf(mx, v);
        sum = sum * fast_exp(mx - nm) + fast_exp(v - nm);
        mx = nm;
    }
    shm[tid] = mx; shs[tid] = sum; __syncthreads();
    for (int s = 512; s > 0; s >>= 1) {
        if (tid < s) {
            float m2 = shm[tid + s], s2 = shs[tid + s];
            float nm = fmaxf(shm[tid], m2);
            shs[tid] = shs[tid] * fast_exp(shm[tid] - nm) + s2 * fast_exp(m2 - nm);
            shm[tid] = nm;
        }
        __syncthreads();
    }
    float lse = shm[0] + logf(shs[0]);

    for (int i = tid; i < VDIM; i += 1024) row[i] -= lse;
}

// ---------------------------------------------------------------------------
// Launcher
// ---------------------------------------------------------------------------
extern "C" void kernel_launch(void* const* d_in, const int* in_sizes, int n_in,
                              void* d_out, int out_size)
{
    (void)in_sizes; (void)n_in; (void)out_size;
    const int*   input = (const int*)  d_in[0];
    const float* h0    = (const float*)d_in[1];
    const float* c0    = (const float*)d_in[2];
    const float* dh0   = (const float*)d_in[3];
    const float* dc0   = (const float*)d_in[4];
    const float* qo    = (const float*)d_in[5];
    const float* enc   = (const float*)d_in[6];
    const float* embed = (const float*)d_in[7];
    const float* W_qa  = (const float*)d_in[8];
    const float* b_qa  = (const float*)d_in[9];
    const float* v_q   = (const float*)d_in[10];
    const float* W_da  = (const float*)d_in[11];
    const float* b_da  = (const float*)d_in[12];
    const float* v_d   = (const float*)d_in[13];
    const float* W_ih  = (const float*)d_in[14];
    const float* W_hh  = (const float*)d_in[15];
    const float* b_ih  = (const float*)d_in[16];
    const float* b_hh  = (const float*)d_in[17];
    const float* Wd_ih = (const float*)d_in[18];
    const float* Wd_hh = (const float*)d_in[19];
    const float* bd_ih = (const float*)d_in[20];
    const float* bd_hh = (const float*)d_in[21];
    const float* W_out = (const float*)d_in[22];
    const float* b_out = (const float*)d_in[23];
    float* out = (float*)d_out;

    float *qpartT, *partq, *docq, *dqpartT, *partd, *xcat, *xout, *skbuf;
    cudaGetSymbolAddress((void**)&qpartT,  g_qpart);
    cudaGetSymbolAddress((void**)&partq,   g_partq);
    cudaGetSymbolAddress((void**)&docq,    g_docq);
    cudaGetSymbolAddress((void**)&dqpartT, g_dqpart);
    cudaGetSymbolAddress((void**)&partd,   g_partd);
    cudaGetSymbolAddress((void**)&xcat,    g_xcat);
    cudaGetSymbolAddress((void**)&xout,    g_xout);
    cudaGetSymbolAddress((void**)&skbuf,   g_skbuf);

    // smem: 3 stages * (128 + BN) rows * 36 floats * 4 B
    const int SM128 = 3 * (128 + 128) * 36 * 4;   // 110592 -> 2 CTAs/SM
    const int SM64  = 3 * (128 +  64) * 36 * 4;   //  82944 -> 2 CTAs/SM
    cudaFuncSetAttribute((const void*)mma_gemm<128, 64, 32, 2>,
                         cudaFuncAttributeMaxDynamicSharedMemorySize, SM128);
    cudaFuncSetAttribute((const void*)mma_gemm<64, 32, 32, 3>,
                         cudaFuncAttributeMaxDynamicSharedMemorySize, SM64);
    cudaFuncSetAttribute((const void*)mma_gemm<64, 32, 32, 1>,
                         cudaFuncAttributeMaxDynamicSharedMemorySize, SM64);

    // (1) embedding gather + h_last copy
    init_misc<<<BATCH, 1024>>>(input, embed, h0, xcat, docq);

    // ---- Query attention ----
    // (2) qpartT[e,b] = sum_k W_qa[e,k] * h0[b,k]   (split-K x8)
    mma_gemm<64, 32, 32, 3><<<dim3(1, 8, 8), 256, SM64>>>(
        W_qa, 2 * HDIM, HDIM, h0, HDIM,
        nullptr, 0, 0, nullptr, 0,
        HDIM, skbuf, 64, nullptr, nullptr, nullptr, nullptr, nullptr);
    // (3)
    sk_reduce<<<HDIM * 64 / 256, 256>>>(skbuf, HDIM, qpartT);
    // (4) fused energy + score partials  (<-- profiled launch)
    mma_gemm<128, 64, 32, 2><<<dim3(8, 16), 256, SM128>>>(
        qo, HDIM, HDIM, W_qa + HDIM, 2 * HDIM,
        nullptr, 0, 0, nullptr, 0,
        LQ * BATCH, nullptr, 0, b_qa, nullptr, qpartT, v_q, partq);
    // (5) fused softmax + query context
    qctx<<<dim3(HDIM / 256, BATCH), 256>>>(partq, qo, docq);

    // ---- Doc attention ----
    // (6)
    mma_gemm<64, 32, 32, 3><<<dim3(1, 8, 8), 256, SM64>>>(
        W_da, 3 * HDIM, 2 * HDIM, docq, 2 * HDIM,
        nullptr, 0, 0, nullptr, 0,
        HDIM, skbuf, 64, nullptr, nullptr, nullptr, nullptr, nullptr);
    // (7)
    sk_reduce<<<HDIM * 64 / 256, 256>>>(skbuf, HDIM, dqpartT);
    // (8) the big fused doc-energy GEMM
    mma_gemm<128, 64, 32, 2><<<dim3(8, 200), 256, SM128>>>(
        enc, HDIM, HDIM, W_da + 2 * HDIM, 3 * HDIM,
        nullptr, 0, 0, nullptr, 0,
        LD * BATCH, nullptr, 0, b_da, nullptr, dqpartT, v_d, partd);
    // (9) fused doc softmax + context + doc_w output
    dctx<<<dim3(HDIM / 256, BATCH), 256>>>(partd, enc, out + OFF_DOCW, xcat, xout);

    // ---- Distraction LSTM ----
    // (10)
    mma_gemm<64, 32, 32, 3><<<dim3(1, 32, 8), 256, SM64>>>(
        Wd_ih, HDIM, HDIM, xcat + 512, 1536,
        Wd_hh, HDIM, HDIM, dh0, HDIM,
        4 * HDIM, skbuf, 64, nullptr, nullptr, nullptr, nullptr, nullptr);
    // (11)
    lstm_from_parts<<<BATCH * HDIM / 256, 256>>>(skbuf, bd_ih, bd_hh, dc0,
                                                 out + OFF_DH, out + OFF_DC, nullptr);

    // ---- Main LSTM ----
    // (12)
    mma_gemm<64, 32, 32, 3><<<dim3(1, 32, 8), 256, SM64>>>(
        W_ih, 1536, 1536, xcat, 1536,
        W_hh, HDIM, HDIM, h0, HDIM,
        4 * HDIM, skbuf, 64, nullptr, nullptr, nullptr, nullptr, nullptr);
    // (13)
    lstm_from_parts<<<BATCH * HDIM / 256, 256>>>(skbuf, b_ih, b_hh, c0,
                                                 out + OFF_H1, out + OFF_C1, xout);

    // ---- Output projection (as out^T: M=V rows, N=64) + log_softmax ----
    // (14)
    mma_gemm<64, 32, 32, 1><<<dim3(1, (VDIM + 127) / 128), 256, SM64>>>(
        W_out, 2 * HDIM, 2 * HDIM, xout, 2 * HDIM,
        nullptr, 0, 0, nullptr, 0,
        VDIM, out, VDIM, b_out, nullptr, nullptr, nullptr, nullptr);
    // (15)
    logsoftmax_rows<<<BATCH, 1024>>>(out);
}

// round 17
// speedup vs baseline: 4.7719x; 1.0189x over previous
#include <cuda_runtime.h>
#include <cstdint>
#include <math.h>

// ---------------------------------------------------------------------------
// Problem constants
// ---------------------------------------------------------------------------
#define BATCH 64
#define HDIM  1024
#define EDIM  512
#define VDIM  50000
#define LQ    32
#define LD    400

// Output layout (tuple concat, float32)
#define OFF_OUT   0
#define OFF_H1    (3200000)
#define OFF_C1    (OFF_H1 + 65536)
#define OFF_DH    (OFF_C1 + 65536)
#define OFF_DC    (OFF_DH + 65536)
#define OFF_DOCW  (OFF_DC + 65536)

#define PARTW 32   // score partials per row: 8 n-blocks x 4 n-warps

// ---------------------------------------------------------------------------
// Scratch (device globals: no allocations allowed)
// ---------------------------------------------------------------------------
__device__ float g_qpart [HDIM * BATCH];            // qpartT[e,b]
__device__ float g_partq [LQ * BATCH * PARTW];
__device__ float g_docq  [BATCH * 2 * HDIM];        // [h_last | q_ctx]
__device__ float g_dqpart[HDIM * BATCH];            // dqpartT[e,b]
__device__ float g_partd [LD * BATCH * PARTW];
__device__ float g_xcat  [BATCH * 1536];            // [embedded(512) | doc_ctx(1024)]
__device__ float g_xout  [BATCH * 2048];            // [h1 | doc_ctx]
__device__ float g_skbuf [8 * 4096 * BATCH];        // split-K partials [z][m][b]

// ---------------------------------------------------------------------------
// Math helpers (fast, MUFU-based)
// ---------------------------------------------------------------------------
__device__ __forceinline__ float fast_exp(float x) { return __expf(x); }
__device__ __forceinline__ float fast_tanh(float x) {
    float e = __expf(-2.f * fabsf(x));
    float t = __fdividef(1.f - e, 1.f + e);
    return copysignf(t, x);
}
__device__ __forceinline__ float sigf(float x) { return __fdividef(1.f, 1.f + __expf(-x)); }

// ---------------------------------------------------------------------------
// PTX helpers (portable: cp.async + mma.sync)
// ---------------------------------------------------------------------------
__device__ __forceinline__ uint32_t smem_u32_of(const void* p) {
    uint32_t a;
    asm("{ .reg .u64 t; cvta.to.shared.u64 t, %1; cvt.u32.u64 %0, t; }" : "=r"(a) : "l"(p));
    return a;
}

__device__ __forceinline__ void cp_async16(uint32_t dst, const void* src, uint32_t sz) {
    asm volatile("cp.async.cg.shared.global [%0], [%1], 16, %2;"
                 :: "r"(dst), "l"(src), "r"(sz) : "memory");
}

// D(16x8) += A(16x8 tf32, row) * B(8x8 tf32, col)
// Raw fp32 bits: HW ignores the low 13 mantissa bits of tf32 operands.
__device__ __forceinline__ void mma_tf32(float* c, const uint32_t* a, const uint32_t* b) {
    asm volatile(
        "mma.sync.aligned.m16n8k8.row.col.f32.tf32.tf32.f32 "
        "{%0,%1,%2,%3}, {%4,%5,%6,%7}, {%8,%9}, {%0,%1,%2,%3};"
        : "+f"(c[0]), "+f"(c[1]), "+f"(c[2]), "+f"(c[3])
        : "r"(a[0]), "r"(a[1]), "r"(a[2]), "r"(a[3]), "r"(b[0]), "r"(b[1]));
}

// ---------------------------------------------------------------------------
// tf32 mma.sync GEMM:  C[M, N] = sum_pairs A_p[M, K_p] * B_p[N, K_p]^T
// BM=128, BK=32, 256 threads = 8 warps arranged (128/WM) x (BN/WN).
// 3-stage cp.async pipeline + in-chunk register fragment double-buffering.
// grid.z splits the K-chunk range (deterministic split-K; z=1 => full K).
// EPI 0: dst[m*ldc + n] = acc + bias1[m] + bias2[m]
// EPI 1: dst[n*ldc + m] = acc + bias1[m]            (transposed store)
// EPI 2: part[m*PARTW + bx*NW + wn] = sum_n tanh(acc + qadd[n*64+(m&63)] + bias1[n])*v[n]
// EPI 3: dst[(z*M + m)*64 + n] = acc                 (raw split-K partial, BN=64)
// ---------------------------------------------------------------------------
template<int BN, int WM, int WN, int EPI>
__global__ __launch_bounds__(256)
void mma_gemm(const float* __restrict__ A1, int lda1, int K1,
              const float* __restrict__ B1, int ldb1,
              const float* __restrict__ A2, int lda2, int K2,
              const float* __restrict__ B2, int ldb2,
              int M,
              float* __restrict__ dst, int ldc,
              const float* __restrict__ bias1, const float* __restrict__ bias2,
              const float* __restrict__ qadd, const float* __restrict__ vvec,
              float* __restrict__ part)
{
    constexpr int MW  = 128 / WM;                 // warps along M
    constexpr int NW  = BN / WN;                  // warps along N
    static_assert(MW * NW == 8, "8 warps");
    constexpr int MT  = WM / 16;
    constexpr int NT  = WN / 8;
    constexpr int AST = 36;                       // smem row stride (floats)
    constexpr int SF  = 128 * AST + BN * AST;     // floats per stage

    extern __shared__ float smem[];
    const uint32_t smem_addr = smem_u32_of(smem);

    const int tid  = threadIdx.x;
    const int w    = tid >> 5;
    const int lane = tid & 31;
    const int g    = lane >> 2;
    const int t    = lane & 3;
    const int wmid = w % MW;
    const int wnid = w / MW;
    const int wm0  = wmid * WM;
    const int wn0  = wnid * WN;
    const int m0   = blockIdx.y * 128;
    const int n0   = blockIdx.x * BN;

    const int nk1 = K1 >> 5;
    const int nk  = nk1 + (K2 >> 5);
    const int ck  = (nk + (int)gridDim.z - 1) / (int)gridDim.z;
    const int c0  = blockIdx.z * ck;
    const int c1  = min(nk, c0 + ck);

    float acc[MT][NT][4];
#pragma unroll
    for (int mt = 0; mt < MT; mt++)
#pragma unroll
        for (int nt = 0; nt < NT; nt++)
#pragma unroll
            for (int j = 0; j < 4; j++) acc[mt][nt][j] = 0.f;

    auto load_chunk = [&](int stage, int c) {
        const float* Ap; const float* Bp; int lda, ldb, koff;
        if (c < nk1) { Ap = A1; Bp = B1; lda = lda1; ldb = ldb1; koff = c * 32; }
        else         { Ap = A2; Bp = B2; lda = lda2; ldb = ldb2; koff = (c - nk1) * 32; }
        const uint32_t sa = smem_addr + stage * SF * 4;
        const uint32_t sb = sa + 128 * AST * 4;
#pragma unroll
        for (int i = 0; i < 4; i++) {             // A: 128 rows x 32 floats
            int seg = i * 256 + tid;
            int row = seg >> 3, c4 = (seg & 7) * 4;
            int gr  = m0 + row;
            int grc = gr < M ? gr : (M - 1);
            cp_async16(sa + (uint32_t)(row * AST + c4) * 4,
                       Ap + (size_t)grc * lda + koff + c4,
                       gr < M ? 16u : 0u);
        }
#pragma unroll
        for (int i = 0; i < BN / 32; i++) {       // B: BN rows x 32 floats
            int seg = i * 256 + tid;
            int row = seg >> 3, c4 = (seg & 7) * 4;
            cp_async16(sb + (uint32_t)(row * AST + c4) * 4,
                       Bp + (size_t)(n0 + row) * ldb + koff + c4, 16u);
        }
        asm volatile("cp.async.commit_group;" ::: "memory");
    };

    load_chunk(0, c0);
    if (c0 + 1 < c1) load_chunk(1, c0 + 1);

    uint32_t arc[MT][4], brc[NT][2], arn[MT][4], brn[NT][2];

#pragma unroll 1
    for (int c = c0; c < c1; c++) {
        const int s = (c - c0) % 3;
        if (c + 2 < c1) load_chunk((s + 2) % 3, c + 2);
        const int rem = c1 - 1 - c;
        if (rem >= 2)      asm volatile("cp.async.wait_group 2;" ::: "memory");
        else if (rem == 1) asm volatile("cp.async.wait_group 1;" ::: "memory");
        else               asm volatile("cp.async.wait_group 0;" ::: "memory");
        __syncthreads();

        const float* sA = smem + s * SF;
        const float* sB = sA + 128 * AST;

        // prologue: fragments for kk=0
#pragma unroll
        for (int mt = 0; mt < MT; mt++) {
            const int r = wm0 + mt * 16 + g;
            arc[mt][0] = __float_as_uint(sA[(r)     * AST + t]);
            arc[mt][1] = __float_as_uint(sA[(r + 8) * AST + t]);
            arc[mt][2] = __float_as_uint(sA[(r)     * AST + t + 4]);
            arc[mt][3] = __float_as_uint(sA[(r + 8) * AST + t + 4]);
        }
#pragma unroll
        for (int nt = 0; nt < NT; nt++) {
            const int r = wn0 + nt * 8 + g;
            brc[nt][0] = __float_as_uint(sB[r * AST + t]);
            brc[nt][1] = __float_as_uint(sB[r * AST + t + 4]);
        }

#pragma unroll
        for (int kk = 0; kk < 4; kk++) {
            if (kk < 3) {                         // prefetch kk+1 fragments
                const int kb = (kk + 1) * 8;
#pragma unroll
                for (int mt = 0; mt < MT; mt++) {
                    const int r = wm0 + mt * 16 + g;
                    arn[mt][0] = __float_as_uint(sA[(r)     * AST + kb + t]);
                    arn[mt][1] = __float_as_uint(sA[(r + 8) * AST + kb + t]);
                    arn[mt][2] = __float_as_uint(sA[(r)     * AST + kb + t + 4]);
                    arn[mt][3] = __float_as_uint(sA[(r + 8) * AST + kb + t + 4]);
                }
#pragma unroll
                for (int nt = 0; nt < NT; nt++) {
                    const int r = wn0 + nt * 8 + g;
                    brn[nt][0] = __float_as_uint(sB[r * AST + kb + t]);
                    brn[nt][1] = __float_as_uint(sB[r * AST + kb + t + 4]);
                }
            }
#pragma unroll
            for (int nt = 0; nt < NT; nt++)
#pragma unroll
                for (int mt = 0; mt < MT; mt++)
                    mma_tf32(acc[mt][nt], arc[mt], brc[nt]);
            if (kk < 3) {
#pragma unroll
                for (int mt = 0; mt < MT; mt++)
#pragma unroll
                    for (int j = 0; j < 4; j++) arc[mt][j] = arn[mt][j];
#pragma unroll
                for (int nt = 0; nt < NT; nt++) {
                    brc[nt][0] = brn[nt][0];
                    brc[nt][1] = brn[nt][1];
                }
            }
        }
        __syncthreads();
    }

    // ---- Epilogue ----
    if constexpr (EPI == 2) {
#pragma unroll
        for (int mt = 0; mt < MT; mt++)
#pragma unroll
            for (int rh = 0; rh < 2; rh++) {
                const int m = m0 + wm0 + mt * 16 + g + rh * 8;
                const int b = m & (BATCH - 1);
                float p = 0.f;
#pragma unroll
                for (int nt = 0; nt < NT; nt++)
#pragma unroll
                    for (int cj = 0; cj < 2; cj++) {
                        const int n = n0 + wn0 + nt * 8 + 2 * t + cj;
                        float e = fast_tanh(acc[mt][nt][rh * 2 + cj]
                                            + qadd[n * BATCH + b] + bias1[n]);
                        p = fmaf(e, vvec[n], p);
                    }
                p += __shfl_xor_sync(0xffffffffu, p, 1);
                p += __shfl_xor_sync(0xffffffffu, p, 2);
                if (t == 0 && m < M)
                    part[(size_t)m * PARTW + blockIdx.x * NW + wnid] = p;
            }
    } else if constexpr (EPI == 3) {
#pragma unroll
        for (int mt = 0; mt < MT; mt++)
#pragma unroll
            for (int rh = 0; rh < 2; rh++) {
                const int m = m0 + wm0 + mt * 16 + g + rh * 8;
                if (m >= M) continue;
#pragma unroll
                for (int nt = 0; nt < NT; nt++) {
                    const int n = wn0 + nt * 8 + 2 * t;
                    float* d = dst + ((size_t)blockIdx.z * M + m) * 64 + n;
                    d[0] = acc[mt][nt][rh * 2 + 0];
                    d[1] = acc[mt][nt][rh * 2 + 1];
                }
            }
    } else {
#pragma unroll
        for (int mt = 0; mt < MT; mt++)
#pragma unroll
            for (int rh = 0; rh < 2; rh++) {
                const int m = m0 + wm0 + mt * 16 + g + rh * 8;
                if (m >= M) continue;
                float bb = 0.f;
                if (bias1) bb += bias1[m];
                if (EPI == 0 && bias2) bb += bias2[m];
#pragma unroll
                for (int nt = 0; nt < NT; nt++) {
                    const int n = n0 + wn0 + nt * 8 + 2 * t;
                    const float v0 = acc[mt][nt][rh * 2 + 0] + bb;
                    const float v1 = acc[mt][nt][rh * 2 + 1] + bb;
                    if constexpr (EPI == 0) {
                        dst[(size_t)m * ldc + n]     = v0;
                        dst[(size_t)m * ldc + n + 1] = v1;
                    } else {
                        dst[(size_t)(n)     * ldc + m] = v0;
                        dst[(size_t)(n + 1) * ldc + m] = v1;
                    }
                }
            }
    }
}

// split-K reduce (no bias): dst[m*64+n] = sum_z sk[(z*M + m)*64 + n]
__global__ void sk_reduce(const float* __restrict__ sk, int M,
                          float* __restrict__ dst)
{
    int idx = blockIdx.x * blockDim.x + threadIdx.x;  // over M*64
    float s = 0.f;
#pragma unroll
    for (int z = 0; z < 8; z++) s += sk[(size_t)z * M * 64 + idx];
    dst[idx] = s;
}

// ---------------------------------------------------------------------------
// Fused helper kernels
// ---------------------------------------------------------------------------
// embedding gather + h_last copy
__global__ void init_misc(const int* __restrict__ idx,
                          const float* __restrict__ embed,
                          const float* __restrict__ h0,
                          float* __restrict__ xcat, float* __restrict__ docq)
{
    int b = blockIdx.x, t = threadIdx.x;              // 1024 threads
    docq[b * 2048 + t] = h0[b * HDIM + t];
    if (t < EDIM) xcat[b * 1536 + t] = embed[(size_t)idx[b] * EDIM + t];
}

__device__ __forceinline__ float sum_part(const float* __restrict__ p) {
    float s = 0.f;
#pragma unroll
    for (int i = 0; i < PARTW; i++) s += p[i];
    return s;
}

// fused query softmax + context: docq[b, 1024+h] = sum_t softmax(s)_t * qo[t,b,h]
__global__ void qctx(const float* __restrict__ part,
                     const float* __restrict__ qo,
                     float* __restrict__ docq)
{
    __shared__ float w[LQ];
    int b = blockIdx.y, tid = threadIdx.x;            // grid (4, 64) x 256
    if (tid < 32) {
        float s = sum_part(part + ((size_t)tid * BATCH + b) * PARTW);
        float mx = s;
#pragma unroll
        for (int o = 16; o; o >>= 1) mx = fmaxf(mx, __shfl_xor_sync(0xffffffffu, mx, o));
        float e = fast_exp(s - mx);
        float sum = e;
#pragma unroll
        for (int o = 16; o; o >>= 1) sum += __shfl_xor_sync(0xffffffffu, sum, o);
        w[tid] = __fdividef(e, sum);
    }
    __syncthreads();
    int h = blockIdx.x * 256 + tid;
    float a = 0.f;
#pragma unroll 4
    for (int t = 0; t < LQ; t++)
        a = fmaf(w[t], qo[((size_t)t * BATCH + b) * HDIM + h], a);
    docq[b * 2048 + 1024 + h] = a;
}

// fused doc softmax + context + doc_w output
__global__ void dctx(const float* __restrict__ part,
                     const float* __restrict__ enc,
                     float* __restrict__ outw,
                     float* __restrict__ xcat, float* __restrict__ xout)
{
    __shared__ float w[LD];
    __shared__ float red[256];
    int b = blockIdx.y, tid = threadIdx.x;            // grid (4, 64) x 256

    float mx = -1e30f;
    for (int t = tid; t < LD; t += 256) {
        float s = sum_part(part + ((size_t)t * BATCH + b) * PARTW);
        w[t] = s;
        mx = fmaxf(mx, s);
    }
    red[tid] = mx; __syncthreads();
    for (int s = 128; s > 0; s >>= 1) { if (tid < s) red[tid] = fmaxf(red[tid], red[tid + s]); __syncthreads(); }
    mx = red[0]; __syncthreads();

    float sum = 0.f;
    for (int t = tid; t < LD; t += 256) sum += fast_exp(w[t] - mx);
    red[tid] = sum; __syncthreads();
    for (int s = 128; s > 0; s >>= 1) { if (tid < s) red[tid] += red[tid + s]; __syncthreads(); }
    float inv = __fdividef(1.f, red[0]);
    __syncthreads();

    for (int t = tid; t < LD; t += 256) {
        float v = fast_exp(w[t] - mx) * inv;
        w[t] = v;
        if (blockIdx.x == 0) outw[b * LD + t] = v;
    }
    __syncthreads();

    int h = blockIdx.x * 256 + tid;
    float a = 0.f;
#pragma unroll 4
    for (int t = 0; t < LD; t++)
        a = fmaf(w[t], enc[((size_t)t * BATCH + b) * HDIM + h], a);
    xcat[b * 1536 + 512 + h]  = a;
    xout[b * 2048 + 1024 + h] = a;
}

// fused split-K reduce + biases + LSTM cell (gate partials in sk, [z][m][b])
__global__ void lstm_from_parts(const float* __restrict__ sk,
                                const float* __restrict__ b1, const float* __restrict__ b2,
                                const float* __restrict__ cprev,
                                float* __restrict__ hout, float* __restrict__ cout,
                                float* __restrict__ hout2)
{
    int idx = blockIdx.x * blockDim.x + threadIdx.x;  // B*H, b fastest
    int b = idx & 63, h = idx >> 6;
    float g4[4];
#pragma unroll
    for (int q = 0; q < 4; q++) {
        int m = q * 1024 + h;
        float s = b1[m] + b2[m];
#pragma unroll
        for (int z = 0; z < 8; z++) s += sk[((size_t)z * 4096 + m) * 64 + b];
        g4[q] = s;
    }
    float i  = sigf(g4[0]);
    float f  = sigf(g4[1]);
    float gg = fast_tanh(g4[2]);
    float o  = sigf(g4[3]);
    float c  = f * cprev[b * HDIM + h] + i * gg;
    float hh = o * fast_tanh(c);
    hout[b * HDIM + h] = hh;
    cout[b * HDIM + h] = c;
    if (hout2) hout2[b * 2048 + h] = hh;
}

// online log-softmax: one read pass for (max, sum), one write pass
__global__ void logsoftmax_rows(float* __restrict__ x)
{
    __shared__ float shm[1024], shs[1024];
    int b = blockIdx.x, tid = threadIdx.x;            // 1024 threads
    float* row = x + (size_t)b * VDIM;

    float mx = -1e30f, sum = 0.f;
    for (int i = tid; i < VDIM; i += 1024) {
        float v = row[i];
        float nm = fmaxf(mx, v);
        sum = sum * fast_exp(mx - nm) + fast_exp(v - nm);
        mx = nm;
    }
    shm[tid] = mx; shs[tid] = sum; __syncthreads();
    for (int s = 512; s > 0; s >>= 1) {
        if (tid < s) {
            float m2 = shm[tid + s], s2 = shs[tid + s];
            float nm = fmaxf(shm[tid], m2);
            shs[tid] = shs[tid] * fast_exp(shm[tid] - nm) + s2 * fast_exp(m2 - nm);
            shm[tid] = nm;
        }
        __syncthreads();
    }
    float lse = shm[0] + logf(shs[0]);

    for (int i = tid; i < VDIM; i += 1024) row[i] -= lse;
}

// ---------------------------------------------------------------------------
// Launcher
// ---------------------------------------------------------------------------
extern "C" void kernel_launch(void* const* d_in, const int* in_sizes, int n_in,
                              void* d_out, int out_size)
{
    (void)in_sizes; (void)n_in; (void)out_size;
    const int*   input = (const int*)  d_in[0];
    const float* h0    = (const float*)d_in[1];
    const float* c0    = (const float*)d_in[2];
    const float* dh0   = (const float*)d_in[3];
    const float* dc0   = (const float*)d_in[4];
    const float* qo    = (const float*)d_in[5];
    const float* enc   = (const float*)d_in[6];
    const float* embed = (const float*)d_in[7];
    const float* W_qa  = (const float*)d_in[8];
    const float* b_qa  = (const float*)d_in[9];
    const float* v_q   = (const float*)d_in[10];
    const float* W_da  = (const float*)d_in[11];
    const float* b_da  = (const float*)d_in[12];
    const float* v_d   = (const float*)d_in[13];
    const float* W_ih  = (const float*)d_in[14];
    const float* W_hh  = (const float*)d_in[15];
    const float* b_ih  = (const float*)d_in[16];
    const float* b_hh  = (const float*)d_in[17];
    const float* Wd_ih = (const float*)d_in[18];
    const float* Wd_hh = (const float*)d_in[19];
    const float* bd_ih = (const float*)d_in[20];
    const float* bd_hh = (const float*)d_in[21];
    const float* W_out = (const float*)d_in[22];
    const float* b_out = (const float*)d_in[23];
    float* out = (float*)d_out;

    float *qpartT, *partq, *docq, *dqpartT, *partd, *xcat, *xout, *skbuf;
    cudaGetSymbolAddress((void**)&qpartT,  g_qpart);
    cudaGetSymbolAddress((void**)&partq,   g_partq);
    cudaGetSymbolAddress((void**)&docq,    g_docq);
    cudaGetSymbolAddress((void**)&dqpartT, g_dqpart);
    cudaGetSymbolAddress((void**)&partd,   g_partd);
    cudaGetSymbolAddress((void**)&xcat,    g_xcat);
    cudaGetSymbolAddress((void**)&xout,    g_xout);
    cudaGetSymbolAddress((void**)&skbuf,   g_skbuf);

    // smem: 3 stages * (128 + BN) rows * 36 floats * 4 B
    const int SM128 = 3 * (128 + 128) * 36 * 4;   // 110592
    const int SM64  = 3 * (128 +  64) * 36 * 4;   //  82944
    cudaFuncSetAttribute((const void*)mma_gemm<128, 64, 32, 2>,
                         cudaFuncAttributeMaxDynamicSharedMemorySize, SM128);
    cudaFuncSetAttribute((const void*)mma_gemm<64, 32, 32, 3>,
                         cudaFuncAttributeMaxDynamicSharedMemorySize, SM64);
    cudaFuncSetAttribute((const void*)mma_gemm<64, 32, 32, 1>,
                         cudaFuncAttributeMaxDynamicSharedMemorySize, SM64);

    // (1) embedding gather + h_last copy
    init_misc<<<BATCH, 1024>>>(input, embed, h0, xcat, docq);

    // ---- Query attention ----
    // (2) qpartT[e,b] = sum_k W_qa[e,k] * h0[b,k]   (split-K x8)
    mma_gemm<64, 32, 32, 3><<<dim3(1, 8, 8), 256, SM64>>>(
        W_qa, 2 * HDIM, HDIM, h0, HDIM,
        nullptr, 0, 0, nullptr, 0,
        HDIM, skbuf, 64, nullptr, nullptr, nullptr, nullptr, nullptr);
    // (3)
    sk_reduce<<<HDIM * 64 / 256, 256>>>(skbuf, HDIM, qpartT);
    // (4) fused energy + score partials  (<-- profiled launch)
    mma_gemm<128, 64, 32, 2><<<dim3(8, 16), 256, SM128>>>(
        qo, HDIM, HDIM, W_qa + HDIM, 2 * HDIM,
        nullptr, 0, 0, nullptr, 0,
        LQ * BATCH, nullptr, 0, b_qa, nullptr, qpartT, v_q, partq);
    // (5) fused softmax + query context
    qctx<<<dim3(HDIM / 256, BATCH), 256>>>(partq, qo, docq);

    // ---- Doc attention ----
    // (6)
    mma_gemm<64, 32, 32, 3><<<dim3(1, 8, 8), 256, SM64>>>(
        W_da, 3 * HDIM, 2 * HDIM, docq, 2 * HDIM,
        nullptr, 0, 0, nullptr, 0,
        HDIM, skbuf, 64, nullptr, nullptr, nullptr, nullptr, nullptr);
    // (7)
    sk_reduce<<<HDIM * 64 / 256, 256>>>(skbuf, HDIM, dqpartT);
    // (8) the big fused doc-energy GEMM
    mma_gemm<128, 64, 32, 2><<<dim3(8, 200), 256, SM128>>>(
        enc, HDIM, HDIM, W_da + 2 * HDIM, 3 * HDIM,
        nullptr, 0, 0, nullptr, 0,
        LD * BATCH, nullptr, 0, b_da, nullptr, dqpartT, v_d, partd);
    // (9) fused doc softmax + context + doc_w output
    dctx<<<dim3(HDIM / 256, BATCH), 256>>>(partd, enc, out + OFF_DOCW, xcat, xout);

    // ---- Distraction LSTM ----
    // (10)
    mma_gemm<64, 32, 32, 3><<<dim3(1, 32, 8), 256, SM64>>>(
        Wd_ih, HDIM, HDIM, xcat + 512, 1536,
        Wd_hh, HDIM, HDIM, dh0, HDIM,
        4 * HDIM, skbuf, 64, nullptr, nullptr, nullptr, nullptr, nullptr);
    // (11)
    lstm_from_parts<<<BATCH * HDIM / 256, 256>>>(skbuf, bd_ih, bd_hh, dc0,
                                                 out + OFF_DH, out + OFF_DC, nullptr);

    // ---- Main LSTM ----
    // (12)
    mma_gemm<64, 32, 32, 3><<<dim3(1, 32, 8), 256, SM64>>>(
        W_ih, 1536, 1536, xcat, 1536,
        W_hh, HDIM, HDIM, h0, HDIM,
        4 * HDIM, skbuf, 64, nullptr, nullptr, nullptr, nullptr, nullptr);
    // (13)
    lstm_from_parts<<<BATCH * HDIM / 256, 256>>>(skbuf, b_ih, b_hh, c0,
                                                 out + OFF_H1, out + OFF_C1, xout);

    // ---- Output projection (as out^T: M=V rows, N=64) + log_softmax ----
    // (14)
    mma_gemm<64, 32, 32, 1><<<dim3(1, (VDIM + 127) / 128), 256, SM64>>>(
        W_out, 2 * HDIM, 2 * HDIM, xout, 2 * HDIM,
        nullptr, 0, 0, nullptr, 0,
        VDIM, out, VDIM, b_out, nullptr, nullptr, nullptr, nullptr);
    // (15)
    logsoftmax_rows<<<BATCH, 1024>>>(out);
}